// round 7
// baseline (speedup 1.0000x reference)
#include <cuda_runtime.h>
#include <cuda_bf16.h>
#include <cuda_fp16.h>
#include <math.h>
#include <stdint.h>

// Problem dims
#define BN_ 128
#define SN_ 1024
#define DN_ 64
#define HN_ 128
#define ON_ 512
#define FK_ 896
#define MTOT_ (BN_ * SN_)   // 131072

// ---------------------------------------------------------------------------
// Scratch (device globals: allocation-free rule)
// ---------------------------------------------------------------------------
__device__ float  g_pt[(size_t)MTOT_ * HN_];     // 64 MB encoded phases
__device__ __half g_f[(size_t)MTOT_ * FK_];      // 235 MB feats fp16
__device__ __half g_w[(size_t)ON_ * FK_];        // Wr fp16
__device__ int    g_rep[SN_];

__device__ __forceinline__ uint32_t smem_u32(const void* p) {
    uint32_t a;
    asm("{ .reg .u64 t; cvta.to.shared.u64 t, %1; cvt.u32.u64 %0, t; }" : "=r"(a) : "l"(p));
    return a;
}
__device__ __forceinline__ void cp16(uint32_t dst, const void* src) {
    asm volatile("cp.async.cg.shared.global [%0], [%1], 16;" :: "r"(dst), "l"(src));
}
#define CP_COMMIT() asm volatile("cp.async.commit_group;" ::: "memory")
#define CP_WAIT(n)  asm volatile("cp.async.wait_group %0;" :: "n"(n) : "memory")
#define SWZ(o) ((o) ^ (((o) >> 3) & 0x70))

__device__ __forceinline__ void ldm4(uint32_t* r, uint32_t addr) {
    asm volatile("ldmatrix.sync.aligned.m8n8.x4.shared.b16 {%0,%1,%2,%3}, [%4];"
        : "=r"(r[0]), "=r"(r[1]), "=r"(r[2]), "=r"(r[3]) : "r"(addr));
}
__device__ __forceinline__ void mma16816(float* d, const uint32_t* a, const uint32_t* b) {
    asm volatile("mma.sync.aligned.m16n8k16.row.col.f32.f16.f16.f32 "
        "{%0,%1,%2,%3}, {%4,%5,%6,%7}, {%8,%9}, {%0,%1,%2,%3};"
        : "+f"(d[0]), "+f"(d[1]), "+f"(d[2]), "+f"(d[3])
        : "r"(a[0]), "r"(a[1]), "r"(a[2]), "r"(a[3]), "r"(b[0]), "r"(b[1]));
}

// ---------------------------------------------------------------------------
// Kernel 1: encoder pt[b,s,h] = x[b,s,:] @ We[h,:] + be[h]  (fp32: feeds the
// sensitive recurrence; keep exact)
// ---------------------------------------------------------------------------
__global__ __launch_bounds__(128) void encoder_kernel(
    const float* __restrict__ x, const float* __restrict__ We,
    const float* __restrict__ be)
{
    __shared__ float sWe[HN_ * 65];
    __shared__ float sx[8 * DN_];
    int tid = threadIdx.x;
    for (int i = tid; i < HN_ * DN_; i += 128)
        sWe[(i >> 6) * 65 + (i & 63)] = We[i];
    int blk = blockIdx.x;
    int b = blk >> 7, sc = blk & 127;
    const float* xp = x + ((size_t)b * SN_ + (size_t)sc * 8) * DN_;
    for (int i = tid; i < 8 * DN_; i += 128) sx[i] = xp[i];
    __syncthreads();
    float bias = be[tid];
    float* ptp = g_pt + ((size_t)b * SN_ + (size_t)sc * 8) * HN_ + tid;
    const float* wrow = &sWe[tid * 65];
#pragma unroll
    for (int s = 0; s < 8; s++) {
        float acc = bias;
#pragma unroll
        for (int d = 0; d < DN_; d++) acc += sx[s * DN_ + d] * wrow[d];
        ptp[(size_t)s * HN_] = acc;
    }
}

// ---------------------------------------------------------------------------
// Kernel 2: repeat flags
// ---------------------------------------------------------------------------
__global__ void rep_kernel(const float* __restrict__ x)
{
    int s = blockIdx.x;
    if (s == 0) { if (threadIdx.x == 0) g_rep[0] = 0; return; }
    int ok = 1;
    for (int i = threadIdx.x; i < BN_ * DN_; i += blockDim.x) {
        int b = i >> 6, d = i & 63;
        size_t base = ((size_t)b * SN_ + s) * DN_ + d;
        if (x[base] != x[base - DN_]) ok = 0;
    }
    ok = __syncthreads_and(ok);
    if (threadIdx.x == 0) g_rep[s] = ok;
}

// ---------------------------------------------------------------------------
// Kernel 3: recurrence. __sinf on the serial critical path (25-cyc dep chain
// vs ~60 for the precise poly). Dynamics are contracting (E[log|1+cos|]<0),
// so the ~3e-5 per-step trig error does not accumulate.
// ---------------------------------------------------------------------------
__global__ __launch_bounds__(256) void recur_state(
    const float* __restrict__ omega,
    float* __restrict__ ph_hist, float* __restrict__ wb_hist)
{
    __shared__ int srep[SN_];
    int tid = threadIdx.x;
    for (int i = tid; i < SN_; i += 256) srep[i] = g_rep[i];
    __syncthreads();

    int idx = blockIdx.x * 256 + tid;
    int b = idx >> 7, h = idx & (HN_ - 1);
    float om = omega[h];
    float ph = 0.0f, wb = 0.0f;
    const float* pp = g_pt + (size_t)b * SN_ * HN_ + h;
    float* php = ph_hist + (size_t)b * SN_ * HN_ + h;
    float* wbp = wb_hist + (size_t)b * SN_ * HN_ + h;

    float pnext = pp[0];
    for (int t = 0; t < SN_; t++) {
        float p = pnext;
        if (t < SN_ - 1) pnext = pp[(size_t)(t + 1) * HN_];
        wb += 0.015625f;
        float drive = om + 0.25f * __sinf(wb);   // off the ph-critical path
        ph = ph + drive - __sinf(p - ph);
        if (srep[t]) wb += 0.25f * __sinf(p - wb);
        php[(size_t)t * HN_] = ph;
        wbp[(size_t)t * HN_] = wb;
    }
}

// ---------------------------------------------------------------------------
// Kernel 4: featurize — 2 adjacent h per thread, __half2 stores, fast trig
// feats [M, 7H]: cos ph | sin ph | cos ph/2 | sin ph/2 | cos wb | sin wb | ph
// ---------------------------------------------------------------------------
__global__ __launch_bounds__(256) void featurize(
    const float* __restrict__ ph_hist, const float* __restrict__ wb_hist)
{
    size_t gid = (size_t)blockIdx.x * 256 + threadIdx.x;   // over M*H/2
    size_t m = gid >> 6;
    int h = (int)(gid & 63) * 2;
    float2 ph = *(const float2*)(ph_hist + m * HN_ + h);
    float2 wb = *(const float2*)(wb_hist + m * HN_ + h);
    float c1a, s1a, c2a, s2a, c3a, s3a, c1b, s1b, c2b, s2b, c3b, s3b;
    __sincosf(ph.x, &s1a, &c1a); __sincosf(ph.y, &s1b, &c1b);
    __sincosf(0.5f * ph.x, &s2a, &c2a); __sincosf(0.5f * ph.y, &s2b, &c2b);
    __sincosf(wb.x, &s3a, &c3a); __sincosf(wb.y, &s3b, &c3b);
    __half2* f = (__half2*)(g_f + m * FK_ + h);
    f[0 * HN_ / 2] = __floats2half2_rn(c1a, c1b);
    f[1 * HN_ / 2] = __floats2half2_rn(s1a, s1b);
    f[2 * HN_ / 2] = __floats2half2_rn(c2a, c2b);
    f[3 * HN_ / 2] = __floats2half2_rn(s2a, s2b);
    f[4 * HN_ / 2] = __floats2half2_rn(c3a, c3b);
    f[5 * HN_ / 2] = __floats2half2_rn(s3a, s3b);
    f[6 * HN_ / 2] = __floats2half2_rn(ph.x, ph.y);
}

// ---------------------------------------------------------------------------
// Kernel 5: Wr -> fp16
// ---------------------------------------------------------------------------
__global__ __launch_bounds__(256) void wconv(const float* __restrict__ Wr)
{
    size_t i = (size_t)blockIdx.x * 256 + threadIdx.x;
    if (i < (size_t)ON_ * FK_) g_w[i] = __float2half(Wr[i]);
}

// ---------------------------------------------------------------------------
// Kernel 6: HMMA GEMM  C[m,o] = feats[m,:] . Wr[o,:] + br[o]
// CTA 128x128, K chunks of 64 fp16 (128B SW128 rows).
// 3-stage cp.async pipeline, ONE __syncthreads per chunk (3 stages make the
// stage-(c-1) WAR hazard covered by the top-of-iteration barrier).
// 8 warps: 4 along M x 2 along N; warp tile 32x64 via m16n8k16.
// ---------------------------------------------------------------------------
#define ASZ   16384
#define STAGE 32768
#define GEMM_SMEM (3 * STAGE + 1024)
#define NCHUNK 14

__global__ __launch_bounds__(256, 2) void gemm_hmma(
    const float* __restrict__ br, float* __restrict__ C)
{
    extern __shared__ char smem[];
    uint32_t sb = (smem_u32(smem) + 1023) & ~1023u;
    int tid = threadIdx.x;
    int lane = tid & 31, wid = tid >> 5;
    int warpM = wid & 3, warpN = wid >> 2;
    int bn = blockIdx.x * 128;                 // N tile (0..3)
    size_t bm = (size_t)blockIdx.y * 128;      // M tile

    const __half* Ab = g_f + bm * FK_;
    const __half* Bb = g_w + (size_t)bn * FK_;

    auto load_chunk = [&](int c) {
        uint32_t stb = sb + (c % 3) * STAGE;
        int k0 = c * 64;
#pragma unroll
        for (int u = tid; u < 1024; u += 256) {
            int row = u >> 3, sg = (u & 7) * 16;
            uint32_t off = SWZ(row * 128 + sg);
            cp16(stb + off, (const char*)(Ab + (size_t)row * FK_ + k0) + sg);
            cp16(stb + ASZ + off, (const char*)(Bb + (size_t)row * FK_ + k0) + sg);
        }
    };

    float acc[2][8][4];
#pragma unroll
    for (int mt = 0; mt < 2; mt++)
#pragma unroll
        for (int f = 0; f < 8; f++)
#pragma unroll
            for (int j = 0; j < 4; j++) acc[mt][f][j] = 0.0f;

    int aRow = warpM * 32 + (lane & 15);
    int aK8  = (lane >> 4);
    int bNr  = warpN * 64 + ((lane >> 4) << 3) + (lane & 7);
    int bK8  = (lane >> 3) & 1;

    load_chunk(0); CP_COMMIT();
    load_chunk(1); CP_COMMIT();

    for (int c = 0; c < NCHUNK; c++) {
        if (c + 1 < NCHUNK) { CP_WAIT(1); } else { CP_WAIT(0); }
        __syncthreads();
        uint32_t stb = sb + (c % 3) * STAGE;
#pragma unroll
        for (int kk = 0; kk < 4; kk++) {
            uint32_t a[2][4], b[4][4];
#pragma unroll
            for (int mt = 0; mt < 2; mt++) {
                int khalf = kk * 16 + aK8 * 8;
                ldm4(a[mt], stb + SWZ((aRow + mt * 16) * 128 + khalf * 2));
            }
#pragma unroll
            for (int np = 0; np < 4; np++) {
                int khalf = kk * 16 + bK8 * 8;
                ldm4(b[np], stb + ASZ + SWZ((bNr + np * 16) * 128 + khalf * 2));
            }
#pragma unroll
            for (int mt = 0; mt < 2; mt++)
#pragma unroll
                for (int np = 0; np < 4; np++) {
                    mma16816(acc[mt][np * 2 + 0], a[mt], &b[np][0]);
                    mma16816(acc[mt][np * 2 + 1], a[mt], &b[np][2]);
                }
        }
        if (c + 2 < NCHUNK) { load_chunk(c + 2); CP_COMMIT(); }
    }

    // epilogue
    int g = lane >> 2, t = lane & 3;
#pragma unroll
    for (int f = 0; f < 8; f++) {
        int col = bn + warpN * 64 + f * 8 + 2 * t;
        float2 bv = *(const float2*)(br + col);
#pragma unroll
        for (int mt = 0; mt < 2; mt++) {
            int r0 = warpM * 32 + mt * 16 + g;
            float* c0 = C + (bm + r0) * (size_t)ON_ + col;
            float* c1 = C + (bm + r0 + 8) * (size_t)ON_ + col;
            float2 v0 = { acc[mt][f][0] + bv.x, acc[mt][f][1] + bv.y };
            float2 v1 = { acc[mt][f][2] + bv.x, acc[mt][f][3] + bv.y };
            *(float2*)c0 = v0;
            *(float2*)c1 = v1;
        }
    }
}

// ---------------------------------------------------------------------------
extern "C" void kernel_launch(void* const* d_in, const int* in_sizes, int n_in,
                              void* d_out, int out_size)
{
    const float* x     = (const float*)d_in[0];
    const float* We    = (const float*)d_in[1];
    const float* be    = (const float*)d_in[2];
    const float* omega = (const float*)d_in[3];
    const float* Wr    = (const float*)d_in[4];
    const float* br    = (const float*)d_in[5];

    float* out     = (float*)d_out;
    float* logits  = out;                                   // [B,S,O]
    float* ph_hist = out + (size_t)MTOT_ * ON_;             // [B,S,H]
    float* wb_hist = ph_hist + (size_t)MTOT_ * HN_;         // [B,S,H]

    cudaFuncSetAttribute(gemm_hmma, cudaFuncAttributeMaxDynamicSharedMemorySize, GEMM_SMEM);

    encoder_kernel<<<BN_ * (SN_ / 8), 128>>>(x, We, be);
    rep_kernel<<<SN_, 256>>>(x);
    recur_state<<<(BN_ * HN_) / 256, 256>>>(omega, ph_hist, wb_hist);
    featurize<<<(MTOT_ * HN_ / 2) / 256, 256>>>(ph_hist, wb_hist);
    wconv<<<(ON_ * FK_ + 255) / 256, 256>>>(Wr);
    gemm_hmma<<<dim3(4, 1024), 256, GEMM_SMEM>>>(br, logits);
}

// round 9
// speedup vs baseline: 1.0061x; 1.0061x over previous
#include <cuda_runtime.h>
#include <cuda_bf16.h>
#include <cuda_fp16.h>
#include <math.h>
#include <stdint.h>

// Problem dims
#define BN_ 128
#define SN_ 1024
#define DN_ 64
#define HN_ 128
#define ON_ 512
#define FK_ 896
#define MTOT_ (BN_ * SN_)   // 131072

// ---------------------------------------------------------------------------
// Scratch (device globals: allocation-free rule)
// ---------------------------------------------------------------------------
__device__ float  g_pt[(size_t)MTOT_ * HN_];     // 64 MB encoded phases
__device__ __half g_f[(size_t)MTOT_ * FK_];      // 235 MB feats fp16
__device__ __half g_w[(size_t)ON_ * FK_];        // Wr fp16
__device__ int    g_rep[SN_];

__device__ __forceinline__ uint32_t smem_u32(const void* p) {
    uint32_t a;
    asm("{ .reg .u64 t; cvta.to.shared.u64 t, %1; cvt.u32.u64 %0, t; }" : "=r"(a) : "l"(p));
    return a;
}
__device__ __forceinline__ void cp16(uint32_t dst, const void* src) {
    asm volatile("cp.async.cg.shared.global [%0], [%1], 16;" :: "r"(dst), "l"(src));
}
#define CP_COMMIT() asm volatile("cp.async.commit_group;" ::: "memory")
#define CP_WAIT(n)  asm volatile("cp.async.wait_group %0;" :: "n"(n) : "memory")
#define SWZ(o) ((o) ^ (((o) >> 3) & 0x70))

__device__ __forceinline__ void ldm4(uint32_t* r, uint32_t addr) {
    asm volatile("ldmatrix.sync.aligned.m8n8.x4.shared.b16 {%0,%1,%2,%3}, [%4];"
        : "=r"(r[0]), "=r"(r[1]), "=r"(r[2]), "=r"(r[3]) : "r"(addr));
}
__device__ __forceinline__ void mma16816(float* d, const uint32_t* a, const uint32_t* b) {
    asm volatile("mma.sync.aligned.m16n8k16.row.col.f32.f16.f16.f32 "
        "{%0,%1,%2,%3}, {%4,%5,%6,%7}, {%8,%9}, {%0,%1,%2,%3};"
        : "+f"(d[0]), "+f"(d[1]), "+f"(d[2]), "+f"(d[3])
        : "r"(a[0]), "r"(a[1]), "r"(a[2]), "r"(a[3]), "r"(b[0]), "r"(b[1]));
}

// ---------------------------------------------------------------------------
// Kernel 1: encoder. One CTA per batch b. 256 thr = 2 s-groups x 128 h.
// We row lives in 64 registers per thread (read once per CTA, 4 MB total).
// ---------------------------------------------------------------------------
__global__ __launch_bounds__(256) void encoder_kernel(
    const float* __restrict__ x, const float* __restrict__ We,
    const float* __restrict__ be)
{
    __shared__ float sx[8 * DN_];
    int tid = threadIdx.x;
    int h = tid & 127, sg = tid >> 7;      // sg in {0,1}
    int b = blockIdx.x;

    float w[DN_];
#pragma unroll
    for (int d = 0; d < DN_; d++) w[d] = We[h * DN_ + d];
    float bias = be[h];

    const float* xb = x + (size_t)b * SN_ * DN_;
    float* ptb = g_pt + (size_t)b * SN_ * HN_;

    for (int sc = 0; sc < SN_ / 8; sc++) {
        __syncthreads();
        if (tid < 128)
            ((float4*)sx)[tid] = ((const float4*)(xb + (size_t)sc * 8 * DN_))[tid];
        __syncthreads();
#pragma unroll
        for (int si = 0; si < 4; si++) {
            int s = sg * 4 + si;
            float acc = bias;
#pragma unroll
            for (int d = 0; d < DN_; d++) acc += sx[s * DN_ + d] * w[d];
            ptb[(size_t)(sc * 8 + s) * HN_ + h] = acc;
        }
    }
}

// ---------------------------------------------------------------------------
// Kernel 2: repeat flags (fast-path single-element precheck) + Wr->fp16,
// merged into one launch via blockIdx split.
// ---------------------------------------------------------------------------
#define WCONV_BLOCKS ((ON_ * FK_ + 255) / 256)
__global__ __launch_bounds__(256) void prep_kernel(
    const float* __restrict__ x, const float* __restrict__ Wr)
{
    if (blockIdx.x < SN_) {
        int s = blockIdx.x;
        if (s == 0) { if (threadIdx.x == 0) g_rep[0] = 0; return; }
        __shared__ int fast;
        if (threadIdx.x == 0)
            fast = (x[(size_t)s * DN_] != x[(size_t)(s - 1) * DN_]);
        __syncthreads();
        if (fast) { if (threadIdx.x == 0) g_rep[s] = 0; return; }
        int ok = 1;
        for (int i = threadIdx.x; i < BN_ * DN_; i += 256) {
            int b = i >> 6, d = i & 63;
            size_t base = ((size_t)b * SN_ + s) * DN_ + d;
            if (x[base] != x[base - DN_]) ok = 0;
        }
        ok = __syncthreads_and(ok);
        if (threadIdx.x == 0) g_rep[s] = ok;
    } else {
        size_t i = (size_t)(blockIdx.x - SN_) * 256 + threadIdx.x;
        if (i < (size_t)ON_ * FK_) g_w[i] = __float2half(Wr[i]);
    }
}

// ---------------------------------------------------------------------------
// Kernel 3: recurrence + featurize fused. One thread per (b,h) chain.
// Critical path: sub -> MUFU.SIN -> sub (~24 cyc). Feature trig + stores are
// off the critical path; DRAM write 363 MB bounds the kernel.
// feats [M, 7H]: cos ph | sin ph | cos ph/2 | sin ph/2 | cos wb | sin wb | ph
// ---------------------------------------------------------------------------
__global__ __launch_bounds__(256) void recur_feat(
    const float* __restrict__ omega,
    float* __restrict__ ph_hist, float* __restrict__ wb_hist)
{
    __shared__ int srep[SN_];
    int tid = threadIdx.x;
    for (int i = tid; i < SN_; i += 256) srep[i] = g_rep[i];
    __syncthreads();

    int idx = blockIdx.x * 256 + tid;
    int b = idx >> 7, h = idx & (HN_ - 1);
    float om = omega[h];
    float ph = 0.0f, wb = 0.0f;
    const float* pp = g_pt + (size_t)b * SN_ * HN_ + h;
    float* php = ph_hist + (size_t)b * SN_ * HN_ + h;
    float* wbp = wb_hist + (size_t)b * SN_ * HN_ + h;
    __half* fp = g_f + (size_t)b * SN_ * FK_ + h;

    float pnext = pp[0];
    for (int t = 0; t < SN_; t++) {
        float p = pnext;
        if (t < SN_ - 1) pnext = pp[(size_t)(t + 1) * HN_];
        wb += 0.015625f;
        float drive = om + 0.25f * __sinf(wb);   // off the ph-critical path
        ph = ph + drive - __sinf(p - ph);
        if (srep[t]) wb += 0.25f * __sinf(p - wb);
        php[(size_t)t * HN_] = ph;
        wbp[(size_t)t * HN_] = wb;
        float c1, s1, c2, s2, c3, s3;
        __sincosf(ph, &s1, &c1);
        __sincosf(0.5f * ph, &s2, &c2);
        __sincosf(wb, &s3, &c3);
        __half* f = fp + (size_t)t * FK_;
        f[0 * HN_] = __float2half(c1);
        f[1 * HN_] = __float2half(s1);
        f[2 * HN_] = __float2half(c2);
        f[3 * HN_] = __float2half(s2);
        f[4 * HN_] = __float2half(c3);
        f[5 * HN_] = __float2half(s3);
        f[6 * HN_] = __float2half(ph);
    }
}

// ---------------------------------------------------------------------------
// Kernel 4: HMMA GEMM  C[m,o] = feats[m,:] . Wr[o,:] + br[o]
// CTA 128x128, K chunks of 64 fp16 (128B SW128 rows). 3-stage cp.async.
// CORRECT ordering: each warp CP_WAITs its own groups, THEN __syncthreads
// (cross-warp visibility), THEN issue load(c+2) (WAR on stage (c-1)%3 is
// covered by the barrier since its MMAs ran in iteration c-1), THEN MMAs —
// so the next-next DMA overlaps this chunk's compute.
// ---------------------------------------------------------------------------
#define ASZ   16384
#define STAGE 32768
#define GEMM_SMEM (3 * STAGE + 1024)
#define NCHUNK 14

__global__ __launch_bounds__(256, 2) void gemm_hmma(
    const float* __restrict__ br, float* __restrict__ C)
{
    extern __shared__ char smem[];
    uint32_t sb = (smem_u32(smem) + 1023) & ~1023u;
    int tid = threadIdx.x;
    int lane = tid & 31, wid = tid >> 5;
    int warpM = wid & 3, warpN = wid >> 2;
    int bn = blockIdx.x * 128;                 // N tile (0..3)
    size_t bm = (size_t)blockIdx.y * 128;      // M tile

    const __half* Ab = g_f + bm * FK_;
    const __half* Bb = g_w + (size_t)bn * FK_;

    auto load_chunk = [&](int c) {
        uint32_t stb = sb + (c % 3) * STAGE;
        int k0 = c * 64;
#pragma unroll
        for (int u = tid; u < 1024; u += 256) {
            int row = u >> 3, sg = (u & 7) * 16;
            uint32_t off = SWZ(row * 128 + sg);
            cp16(stb + off, (const char*)(Ab + (size_t)row * FK_ + k0) + sg);
            cp16(stb + ASZ + off, (const char*)(Bb + (size_t)row * FK_ + k0) + sg);
        }
    };

    float acc[2][8][4];
#pragma unroll
    for (int mt = 0; mt < 2; mt++)
#pragma unroll
        for (int f = 0; f < 8; f++)
#pragma unroll
            for (int j = 0; j < 4; j++) acc[mt][f][j] = 0.0f;

    int aRow = warpM * 32 + (lane & 15);
    int aK8  = (lane >> 4);
    int bNr  = warpN * 64 + ((lane >> 4) << 3) + (lane & 7);
    int bK8  = (lane >> 3) & 1;

    load_chunk(0); CP_COMMIT();
    load_chunk(1); CP_COMMIT();

    for (int c = 0; c < NCHUNK; c++) {
        if (c + 1 < NCHUNK) { CP_WAIT(1); } else { CP_WAIT(0); }
        __syncthreads();
        if (c + 2 < NCHUNK) { load_chunk(c + 2); CP_COMMIT(); }
        uint32_t stb = sb + (c % 3) * STAGE;
#pragma unroll
        for (int kk = 0; kk < 4; kk++) {
            uint32_t a[2][4], b[4][4];
#pragma unroll
            for (int mt = 0; mt < 2; mt++) {
                int khalf = kk * 16 + aK8 * 8;
                ldm4(a[mt], stb + SWZ((aRow + mt * 16) * 128 + khalf * 2));
            }
#pragma unroll
            for (int np = 0; np < 4; np++) {
                int khalf = kk * 16 + bK8 * 8;
                ldm4(b[np], stb + ASZ + SWZ((bNr + np * 16) * 128 + khalf * 2));
            }
#pragma unroll
            for (int mt = 0; mt < 2; mt++)
#pragma unroll
                for (int np = 0; np < 4; np++) {
                    mma16816(acc[mt][np * 2 + 0], a[mt], &b[np][0]);
                    mma16816(acc[mt][np * 2 + 1], a[mt], &b[np][2]);
                }
        }
    }

    // epilogue
    int g = lane >> 2, t = lane & 3;
#pragma unroll
    for (int f = 0; f < 8; f++) {
        int col = bn + warpN * 64 + f * 8 + 2 * t;
        float2 bv = *(const float2*)(br + col);
#pragma unroll
        for (int mt = 0; mt < 2; mt++) {
            int r0 = warpM * 32 + mt * 16 + g;
            float* c0 = C + (bm + r0) * (size_t)ON_ + col;
            float* c1 = C + (bm + r0 + 8) * (size_t)ON_ + col;
            float2 v0 = { acc[mt][f][0] + bv.x, acc[mt][f][1] + bv.y };
            float2 v1 = { acc[mt][f][2] + bv.x, acc[mt][f][3] + bv.y };
            *(float2*)c0 = v0;
            *(float2*)c1 = v1;
        }
    }
}

// ---------------------------------------------------------------------------
extern "C" void kernel_launch(void* const* d_in, const int* in_sizes, int n_in,
                              void* d_out, int out_size)
{
    const float* x     = (const float*)d_in[0];
    const float* We    = (const float*)d_in[1];
    const float* be    = (const float*)d_in[2];
    const float* omega = (const float*)d_in[3];
    const float* Wr    = (const float*)d_in[4];
    const float* br    = (const float*)d_in[5];

    float* out     = (float*)d_out;
    float* logits  = out;                                   // [B,S,O]
    float* ph_hist = out + (size_t)MTOT_ * ON_;             // [B,S,H]
    float* wb_hist = ph_hist + (size_t)MTOT_ * HN_;         // [B,S,H]

    cudaFuncSetAttribute(gemm_hmma, cudaFuncAttributeMaxDynamicSharedMemorySize, GEMM_SMEM);

    encoder_kernel<<<BN_, 256>>>(x, We, be);
    prep_kernel<<<SN_ + WCONV_BLOCKS, 256>>>(x, Wr);
    recur_feat<<<(BN_ * HN_) / 256, 256>>>(omega, ph_hist, wb_hist);
    gemm_hmma<<<dim3(4, 1024), 256, GEMM_SMEM>>>(br, logits);
}

// round 11
// speedup vs baseline: 1.1094x; 1.1027x over previous
#include <cuda_runtime.h>
#include <cuda_bf16.h>
#include <cuda_fp16.h>
#include <math.h>
#include <stdint.h>

// Problem dims
#define BN_ 128
#define SN_ 1024
#define DN_ 64
#define HN_ 128
#define ON_ 512
#define FK_ 896
#define MTOT_ (BN_ * SN_)   // 131072

// ---------------------------------------------------------------------------
// Scratch (device globals: allocation-free rule)
// ---------------------------------------------------------------------------
__device__ float  g_pt[(size_t)MTOT_ * HN_];     // 64 MB encoded phases
__device__ __half g_f[(size_t)MTOT_ * FK_];      // 235 MB feats fp16
__device__ __half g_w[(size_t)ON_ * FK_];        // Wr fp16
__device__ int    g_rep[SN_];

__device__ __forceinline__ uint32_t smem_u32(const void* p) {
    uint32_t a;
    asm("{ .reg .u64 t; cvta.to.shared.u64 t, %1; cvt.u32.u64 %0, t; }" : "=r"(a) : "l"(p));
    return a;
}
__device__ __forceinline__ void cp16(uint32_t dst, const void* src) {
    asm volatile("cp.async.cg.shared.global [%0], [%1], 16;" :: "r"(dst), "l"(src));
}
#define CP_COMMIT() asm volatile("cp.async.commit_group;" ::: "memory")
#define CP_WAIT(n)  asm volatile("cp.async.wait_group %0;" :: "n"(n) : "memory")
#define SWZ(o) ((o) ^ (((o) >> 3) & 0x70))

__device__ __forceinline__ void ldm4(uint32_t* r, uint32_t addr) {
    asm volatile("ldmatrix.sync.aligned.m8n8.x4.shared.b16 {%0,%1,%2,%3}, [%4];"
        : "=r"(r[0]), "=r"(r[1]), "=r"(r[2]), "=r"(r[3]) : "r"(addr));
}
__device__ __forceinline__ void mma16816(float* d, const uint32_t* a, const uint32_t* b) {
    asm volatile("mma.sync.aligned.m16n8k16.row.col.f32.f16.f16.f32 "
        "{%0,%1,%2,%3}, {%4,%5,%6,%7}, {%8,%9}, {%0,%1,%2,%3};"
        : "+f"(d[0]), "+f"(d[1]), "+f"(d[2]), "+f"(d[3])
        : "r"(a[0]), "r"(a[1]), "r"(a[2]), "r"(a[3]), "r"(b[0]), "r"(b[1]));
}

// ---------------------------------------------------------------------------
// Kernel 1: encoder. Thread-per-(b,s) row: x row in 64 registers, We in smem
// (broadcast LDS.128 -> 1 LDS : 4 FFMA), 512 CTAs = full chip, fp32 exact.
// ---------------------------------------------------------------------------
__global__ __launch_bounds__(256) void encoder_kernel(
    const float* __restrict__ x, const float* __restrict__ We,
    const float* __restrict__ be)
{
    __shared__ float4 sWe[HN_ * (DN_ / 4)];   // 32 KB, [h][d4]
    __shared__ float  sbe[HN_];
    int tid = threadIdx.x;

    for (int i = tid; i < HN_ * (DN_ / 4); i += 256)
        sWe[i] = ((const float4*)We)[i];
    if (tid < HN_) sbe[tid] = be[tid];

    size_t m = (size_t)blockIdx.x * 256 + tid;    // (b,s) row id
    float4 xr[DN_ / 4];
    const float4* xp = (const float4*)(x + m * DN_);
#pragma unroll
    for (int i = 0; i < DN_ / 4; i++) xr[i] = xp[i];
    __syncthreads();

    float* out = g_pt + m * HN_;
#pragma unroll 2
    for (int h0 = 0; h0 < HN_; h0 += 4) {
        float4 accv;
        float* acc = (float*)&accv;
#pragma unroll
        for (int j = 0; j < 4; j++) {
            int h = h0 + j;
            float a = sbe[h];
            const float4* wrow = &sWe[h * (DN_ / 4)];
#pragma unroll
            for (int i = 0; i < DN_ / 4; i++) {
                float4 w = wrow[i];
                a += xr[i].x * w.x + xr[i].y * w.y + xr[i].z * w.z + xr[i].w * w.w;
            }
            acc[j] = a;
        }
        *(float4*)(out + h0) = accv;
    }
}

// ---------------------------------------------------------------------------
// Kernel 2: repeat flags (fast-path precheck) + Wr->fp16, merged launch.
// ---------------------------------------------------------------------------
#define WCONV_BLOCKS ((ON_ * FK_ + 255) / 256)
__global__ __launch_bounds__(256) void prep_kernel(
    const float* __restrict__ x, const float* __restrict__ Wr)
{
    if (blockIdx.x < SN_) {
        int s = blockIdx.x;
        if (s == 0) { if (threadIdx.x == 0) g_rep[0] = 0; return; }
        __shared__ int fast;
        if (threadIdx.x == 0)
            fast = (x[(size_t)s * DN_] != x[(size_t)(s - 1) * DN_]);
        __syncthreads();
        if (fast) { if (threadIdx.x == 0) g_rep[s] = 0; return; }
        int ok = 1;
        for (int i = threadIdx.x; i < BN_ * DN_; i += 256) {
            int b = i >> 6, d = i & 63;
            size_t base = ((size_t)b * SN_ + s) * DN_ + d;
            if (x[base] != x[base - DN_]) ok = 0;
        }
        ok = __syncthreads_and(ok);
        if (threadIdx.x == 0) g_rep[s] = ok;
    } else {
        size_t i = (size_t)(blockIdx.x - SN_) * 256 + threadIdx.x;
        if (i < (size_t)ON_ * FK_) g_w[i] = __float2half(Wr[i]);
    }
}

// ---------------------------------------------------------------------------
// Kernel 3: recurrence state only (identical math to R7/R9 passing runs)
// ---------------------------------------------------------------------------
__global__ __launch_bounds__(256) void recur_state(
    const float* __restrict__ omega,
    float* __restrict__ ph_hist, float* __restrict__ wb_hist)
{
    __shared__ int srep[SN_];
    int tid = threadIdx.x;
    for (int i = tid; i < SN_; i += 256) srep[i] = g_rep[i];
    __syncthreads();

    int idx = blockIdx.x * 256 + tid;
    int b = idx >> 7, h = idx & (HN_ - 1);
    float om = omega[h];
    float ph = 0.0f, wb = 0.0f;
    const float* pp = g_pt + (size_t)b * SN_ * HN_ + h;
    float* php = ph_hist + (size_t)b * SN_ * HN_ + h;
    float* wbp = wb_hist + (size_t)b * SN_ * HN_ + h;

    float pnext = pp[0];
    for (int t = 0; t < SN_; t++) {
        float p = pnext;
        if (t < SN_ - 1) pnext = pp[(size_t)(t + 1) * HN_];
        wb += 0.015625f;
        float drive = om + 0.25f * __sinf(wb);   // off the ph-critical path
        ph = ph + drive - __sinf(p - ph);
        if (srep[t]) wb += 0.25f * __sinf(p - wb);
        php[(size_t)t * HN_] = ph;
        wbp[(size_t)t * HN_] = wb;
    }
}

// ---------------------------------------------------------------------------
// Kernel 4: featurize — full-grid (32768 CTAs), DRAM-bound (~52us measured)
// feats [M, 7H]: cos ph | sin ph | cos ph/2 | sin ph/2 | cos wb | sin wb | ph
// ---------------------------------------------------------------------------
__global__ __launch_bounds__(256) void featurize(
    const float* __restrict__ ph_hist, const float* __restrict__ wb_hist)
{
    size_t gid = (size_t)blockIdx.x * 256 + threadIdx.x;   // over M*H/2
    size_t m = gid >> 6;
    int h = (int)(gid & 63) * 2;
    float2 ph = *(const float2*)(ph_hist + m * HN_ + h);
    float2 wb = *(const float2*)(wb_hist + m * HN_ + h);
    float c1a, s1a, c2a, s2a, c3a, s3a, c1b, s1b, c2b, s2b, c3b, s3b;
    __sincosf(ph.x, &s1a, &c1a); __sincosf(ph.y, &s1b, &c1b);
    __sincosf(0.5f * ph.x, &s2a, &c2a); __sincosf(0.5f * ph.y, &s2b, &c2b);
    __sincosf(wb.x, &s3a, &c3a); __sincosf(wb.y, &s3b, &c3b);
    __half2* f = (__half2*)(g_f + m * FK_ + h);
    f[0 * HN_ / 2] = __floats2half2_rn(c1a, c1b);
    f[1 * HN_ / 2] = __floats2half2_rn(s1a, s1b);
    f[2 * HN_ / 2] = __floats2half2_rn(c2a, c2b);
    f[3 * HN_ / 2] = __floats2half2_rn(s2a, s2b);
    f[4 * HN_ / 2] = __floats2half2_rn(c3a, c3b);
    f[5 * HN_ / 2] = __floats2half2_rn(s3a, s3b);
    f[6 * HN_ / 2] = __floats2half2_rn(ph.x, ph.y);
}

// ---------------------------------------------------------------------------
// Kernel 5: HMMA GEMM (unchanged from R9: 278us, tensor=72%)
// ---------------------------------------------------------------------------
#define ASZ   16384
#define STAGE 32768
#define GEMM_SMEM (3 * STAGE + 1024)
#define NCHUNK 14

__global__ __launch_bounds__(256, 2) void gemm_hmma(
    const float* __restrict__ br, float* __restrict__ C)
{
    extern __shared__ char smem[];
    uint32_t sb = (smem_u32(smem) + 1023) & ~1023u;
    int tid = threadIdx.x;
    int lane = tid & 31, wid = tid >> 5;
    int warpM = wid & 3, warpN = wid >> 2;
    int bn = blockIdx.x * 128;                 // N tile (0..3)
    size_t bm = (size_t)blockIdx.y * 128;      // M tile

    const __half* Ab = g_f + bm * FK_;
    const __half* Bb = g_w + (size_t)bn * FK_;

    auto load_chunk = [&](int c) {
        uint32_t stb = sb + (c % 3) * STAGE;
        int k0 = c * 64;
#pragma unroll
        for (int u = tid; u < 1024; u += 256) {
            int row = u >> 3, sg = (u & 7) * 16;
            uint32_t off = SWZ(row * 128 + sg);
            cp16(stb + off, (const char*)(Ab + (size_t)row * FK_ + k0) + sg);
            cp16(stb + ASZ + off, (const char*)(Bb + (size_t)row * FK_ + k0) + sg);
        }
    };

    float acc[2][8][4];
#pragma unroll
    for (int mt = 0; mt < 2; mt++)
#pragma unroll
        for (int f = 0; f < 8; f++)
#pragma unroll
            for (int j = 0; j < 4; j++) acc[mt][f][j] = 0.0f;

    int aRow = warpM * 32 + (lane & 15);
    int aK8  = (lane >> 4);
    int bNr  = warpN * 64 + ((lane >> 4) << 3) + (lane & 7);
    int bK8  = (lane >> 3) & 1;

    load_chunk(0); CP_COMMIT();
    load_chunk(1); CP_COMMIT();

    for (int c = 0; c < NCHUNK; c++) {
        if (c + 1 < NCHUNK) { CP_WAIT(1); } else { CP_WAIT(0); }
        __syncthreads();
        if (c + 2 < NCHUNK) { load_chunk(c + 2); CP_COMMIT(); }
        uint32_t stb = sb + (c % 3) * STAGE;
#pragma unroll
        for (int kk = 0; kk < 4; kk++) {
            uint32_t a[2][4], b[4][4];
#pragma unroll
            for (int mt = 0; mt < 2; mt++) {
                int khalf = kk * 16 + aK8 * 8;
                ldm4(a[mt], stb + SWZ((aRow + mt * 16) * 128 + khalf * 2));
            }
#pragma unroll
            for (int np = 0; np < 4; np++) {
                int khalf = kk * 16 + bK8 * 8;
                ldm4(b[np], stb + ASZ + SWZ((bNr + np * 16) * 128 + khalf * 2));
            }
#pragma unroll
            for (int mt = 0; mt < 2; mt++)
#pragma unroll
                for (int np = 0; np < 4; np++) {
                    mma16816(acc[mt][np * 2 + 0], a[mt], &b[np][0]);
                    mma16816(acc[mt][np * 2 + 1], a[mt], &b[np][2]);
                }
        }
    }

    // epilogue
    int g = lane >> 2, t = lane & 3;
#pragma unroll
    for (int f = 0; f < 8; f++) {
        int col = bn + warpN * 64 + f * 8 + 2 * t;
        float2 bv = *(const float2*)(br + col);
#pragma unroll
        for (int mt = 0; mt < 2; mt++) {
            int r0 = warpM * 32 + mt * 16 + g;
            float* c0 = C + (bm + r0) * (size_t)ON_ + col;
            float* c1 = C + (bm + r0 + 8) * (size_t)ON_ + col;
            float2 v0 = { acc[mt][f][0] + bv.x, acc[mt][f][1] + bv.y };
            float2 v1 = { acc[mt][f][2] + bv.x, acc[mt][f][3] + bv.y };
            *(float2*)c0 = v0;
            *(float2*)c1 = v1;
        }
    }
}

// ---------------------------------------------------------------------------
extern "C" void kernel_launch(void* const* d_in, const int* in_sizes, int n_in,
                              void* d_out, int out_size)
{
    const float* x     = (const float*)d_in[0];
    const float* We    = (const float*)d_in[1];
    const float* be    = (const float*)d_in[2];
    const float* omega = (const float*)d_in[3];
    const float* Wr    = (const float*)d_in[4];
    const float* br    = (const float*)d_in[5];

    float* out     = (float*)d_out;
    float* logits  = out;                                   // [B,S,O]
    float* ph_hist = out + (size_t)MTOT_ * ON_;             // [B,S,H]
    float* wb_hist = ph_hist + (size_t)MTOT_ * HN_;         // [B,S,H]

    cudaFuncSetAttribute(gemm_hmma, cudaFuncAttributeMaxDynamicSharedMemorySize, GEMM_SMEM);

    encoder_kernel<<<MTOT_ / 256, 256>>>(x, We, be);
    prep_kernel<<<SN_ + WCONV_BLOCKS, 256>>>(x, Wr);
    recur_state<<<(BN_ * HN_) / 256, 256>>>(omega, ph_hist, wb_hist);
    featurize<<<(MTOT_ * HN_ / 2) / 256, 256>>>(ph_hist, wb_hist);
    gemm_hmma<<<dim3(4, 1024), 256, GEMM_SMEM>>>(br, logits);
}

// round 13
// speedup vs baseline: 1.3793x; 1.2432x over previous
#include <cuda_runtime.h>
#include <cuda_bf16.h>
#include <cuda_fp16.h>
#include <math.h>
#include <stdint.h>

// Problem dims
#define BN_ 128
#define SN_ 1024
#define DN_ 64
#define HN_ 128
#define ON_ 512
#define FK_ 896
#define MTOT_ (BN_ * SN_)   // 131072

// ---------------------------------------------------------------------------
// Scratch (device globals: allocation-free rule)
// ---------------------------------------------------------------------------
__device__ float  g_pt[(size_t)MTOT_ * HN_];     // 64 MB encoded phases
__device__ __half g_f[(size_t)MTOT_ * FK_];      // 235 MB feats fp16
__device__ __half g_w[(size_t)ON_ * FK_];        // Wr fp16
__device__ int    g_rep[SN_];
__device__ float  g_swb[SN_];                    // 0.25*sin(nominal wb[t])

__device__ __forceinline__ uint32_t smem_u32(const void* p) {
    uint32_t a;
    asm("{ .reg .u64 t; cvta.to.shared.u64 t, %1; cvt.u32.u64 %0, t; }" : "=r"(a) : "l"(p));
    return a;
}
__device__ __forceinline__ void cp16(uint32_t dst, const void* src) {
    asm volatile("cp.async.cg.shared.global [%0], [%1], 16;" :: "r"(dst), "l"(src));
}
#define CP_COMMIT() asm volatile("cp.async.commit_group;" ::: "memory")
#define CP_WAIT(n)  asm volatile("cp.async.wait_group %0;" :: "n"(n) : "memory")
#define SWZ(o) ((o) ^ (((o) >> 3) & 0x70))

__device__ __forceinline__ void ldm4(uint32_t* r, uint32_t addr) {
    asm volatile("ldmatrix.sync.aligned.m8n8.x4.shared.b16 {%0,%1,%2,%3}, [%4];"
        : "=r"(r[0]), "=r"(r[1]), "=r"(r[2]), "=r"(r[3]) : "r"(addr));
}
__device__ __forceinline__ void mma16816(float* d, const uint32_t* a, const uint32_t* b) {
    asm volatile("mma.sync.aligned.m16n8k16.row.col.f32.f16.f16.f32 "
        "{%0,%1,%2,%3}, {%4,%5,%6,%7}, {%8,%9}, {%0,%1,%2,%3};"
        : "+f"(d[0]), "+f"(d[1]), "+f"(d[2]), "+f"(d[3])
        : "r"(a[0]), "r"(a[1]), "r"(a[2]), "r"(a[3]), "r"(b[0]), "r"(b[1]));
}

// ---------------------------------------------------------------------------
// Kernel 1: encoder. Thread-per-(b,s) row, x in 64 regs, We broadcast LDS.
// ---------------------------------------------------------------------------
__global__ __launch_bounds__(256) void encoder_kernel(
    const float* __restrict__ x, const float* __restrict__ We,
    const float* __restrict__ be)
{
    __shared__ float4 sWe[HN_ * (DN_ / 4)];   // 32 KB, [h][d4]
    __shared__ float  sbe[HN_];
    int tid = threadIdx.x;

    for (int i = tid; i < HN_ * (DN_ / 4); i += 256)
        sWe[i] = ((const float4*)We)[i];
    if (tid < HN_) sbe[tid] = be[tid];

    size_t m = (size_t)blockIdx.x * 256 + tid;    // (b,s) row id
    float4 xr[DN_ / 4];
    const float4* xp = (const float4*)(x + m * DN_);
#pragma unroll
    for (int i = 0; i < DN_ / 4; i++) xr[i] = xp[i];
    __syncthreads();

    float* out = g_pt + m * HN_;
#pragma unroll 2
    for (int h0 = 0; h0 < HN_; h0 += 4) {
        float4 accv;
        float* acc = (float*)&accv;
#pragma unroll
        for (int j = 0; j < 4; j++) {
            int h = h0 + j;
            float a = sbe[h];
            const float4* wrow = &sWe[h * (DN_ / 4)];
#pragma unroll
            for (int i = 0; i < DN_ / 4; i++) {
                float4 w = wrow[i];
                a += xr[i].x * w.x + xr[i].y * w.y + xr[i].z * w.z + xr[i].w * w.w;
            }
            acc[j] = a;
        }
        *(float4*)(out + h0) = accv;
    }
}

// ---------------------------------------------------------------------------
// Kernel 2: repeat flags (fast-path precheck) + nominal-wb sin table.
// Nominal wb[t] = (t+1)*2^-6 is EXACT in fp32 (matches the accumulated
// sequence bit-for-bit), so 0.25*__sinf(wb[t]) is chain-independent until a
// repeat occurs; recur falls back to live evaluation after divergence.
// ---------------------------------------------------------------------------
__global__ __launch_bounds__(256) void rep_kernel(const float* __restrict__ x)
{
    if (blockIdx.x >= SN_) {   // table blocks
        int t = (blockIdx.x - SN_) * 256 + threadIdx.x;
        if (t < SN_) g_swb[t] = 0.25f * __sinf((float)(t + 1) * 0.015625f);
        return;
    }
    int s = blockIdx.x;
    if (s == 0) { if (threadIdx.x == 0) g_rep[0] = 0; return; }
    __shared__ int fast;
    if (threadIdx.x == 0)
        fast = (x[(size_t)s * DN_] != x[(size_t)(s - 1) * DN_]);
    __syncthreads();
    if (fast) { if (threadIdx.x == 0) g_rep[s] = 0; return; }
    int ok = 1;
    for (int i = threadIdx.x; i < BN_ * DN_; i += 256) {
        int b = i >> 6, d = i & 63;
        size_t base = ((size_t)b * SN_ + s) * DN_ + d;
        if (x[base] != x[base - DN_]) ok = 0;
    }
    ok = __syncthreads_and(ok);
    if (threadIdx.x == 0) g_rep[s] = ok;
}

// ---------------------------------------------------------------------------
// Kernel 3: Wr -> fp16 (separate launch so recur lands at launch index 4
// for the ncu capture window)
// ---------------------------------------------------------------------------
__global__ __launch_bounds__(256) void wconv(const float* __restrict__ Wr)
{
    size_t i = (size_t)blockIdx.x * 256 + threadIdx.x;
    if (i < (size_t)ON_ * FK_) g_w[i] = __float2half(Wr[i]);
}

// ---------------------------------------------------------------------------
// Kernel 4: recurrence. 8-deep register prefetch ring on g_pt (slack ~8x30
// cycles >= L2 latency; the 1-step prefetch was the 150-300us stall source).
// wb drive from table while undiverged (uniform flag). 128-thr blocks ->
// 128 CTAs so more SMs carry the chains.
// ---------------------------------------------------------------------------
__global__ __launch_bounds__(128) void recur_state(
    const float* __restrict__ omega,
    float* __restrict__ ph_hist, float* __restrict__ wb_hist)
{
    __shared__ int   srep[SN_];
    __shared__ float sswb[SN_];
    int tid = threadIdx.x;
    for (int i = tid; i < SN_; i += 128) { srep[i] = g_rep[i]; sswb[i] = g_swb[i]; }
    __syncthreads();

    int idx = blockIdx.x * 128 + tid;
    int b = idx >> 7, h = idx & (HN_ - 1);
    float om = omega[h];
    float ph = 0.0f, wb = 0.0f;
    bool diverged = false;   // block-uniform (srep is uniform)
    const float* pp = g_pt + (size_t)b * SN_ * HN_ + h;
    float* php = ph_hist + (size_t)b * SN_ * HN_ + h;
    float* wbp = wb_hist + (size_t)b * SN_ * HN_ + h;

    float buf[8];
#pragma unroll
    for (int j = 0; j < 8; j++) buf[j] = pp[(size_t)j * HN_];

    for (int t0 = 0; t0 < SN_; t0 += 8) {
#pragma unroll
        for (int j = 0; j < 8; j++) {
            int t = t0 + j;
            float p = buf[j];
            if (t + 8 < SN_) buf[j] = pp[(size_t)(t + 8) * HN_];   // deep prefetch
            wb += 0.015625f;
            float swb = diverged ? 0.25f * __sinf(wb) : sswb[t];
            ph = ph + (om + swb) - __sinf(p - ph);
            if (srep[t]) { wb += 0.25f * __sinf(p - wb); diverged = true; }
            php[(size_t)t * HN_] = ph;
            wbp[(size_t)t * HN_] = wb;
        }
    }
}

// ---------------------------------------------------------------------------
// Kernel 5: featurize — full-grid, DRAM-bound (52us measured)
// feats [M, 7H]: cos ph | sin ph | cos ph/2 | sin ph/2 | cos wb | sin wb | ph
// ---------------------------------------------------------------------------
__global__ __launch_bounds__(256) void featurize(
    const float* __restrict__ ph_hist, const float* __restrict__ wb_hist)
{
    size_t gid = (size_t)blockIdx.x * 256 + threadIdx.x;   // over M*H/2
    size_t m = gid >> 6;
    int h = (int)(gid & 63) * 2;
    float2 ph = *(const float2*)(ph_hist + m * HN_ + h);
    float2 wb = *(const float2*)(wb_hist + m * HN_ + h);
    float c1a, s1a, c2a, s2a, c3a, s3a, c1b, s1b, c2b, s2b, c3b, s3b;
    __sincosf(ph.x, &s1a, &c1a); __sincosf(ph.y, &s1b, &c1b);
    __sincosf(0.5f * ph.x, &s2a, &c2a); __sincosf(0.5f * ph.y, &s2b, &c2b);
    __sincosf(wb.x, &s3a, &c3a); __sincosf(wb.y, &s3b, &c3b);
    __half2* f = (__half2*)(g_f + m * FK_ + h);
    f[0 * HN_ / 2] = __floats2half2_rn(c1a, c1b);
    f[1 * HN_ / 2] = __floats2half2_rn(s1a, s1b);
    f[2 * HN_ / 2] = __floats2half2_rn(c2a, c2b);
    f[3 * HN_ / 2] = __floats2half2_rn(s2a, s2b);
    f[4 * HN_ / 2] = __floats2half2_rn(c3a, c3b);
    f[5 * HN_ / 2] = __floats2half2_rn(s3a, s3b);
    f[6 * HN_ / 2] = __floats2half2_rn(ph.x, ph.y);
}

// ---------------------------------------------------------------------------
// Kernel 6: HMMA GEMM (unchanged: 278us measured, tensor=72%)
// ---------------------------------------------------------------------------
#define ASZ   16384
#define STAGE 32768
#define GEMM_SMEM (3 * STAGE + 1024)
#define NCHUNK 14

__global__ __launch_bounds__(256, 2) void gemm_hmma(
    const float* __restrict__ br, float* __restrict__ C)
{
    extern __shared__ char smem[];
    uint32_t sb = (smem_u32(smem) + 1023) & ~1023u;
    int tid = threadIdx.x;
    int lane = tid & 31, wid = tid >> 5;
    int warpM = wid & 3, warpN = wid >> 2;
    int bn = blockIdx.x * 128;                 // N tile (0..3)
    size_t bm = (size_t)blockIdx.y * 128;      // M tile

    const __half* Ab = g_f + bm * FK_;
    const __half* Bb = g_w + (size_t)bn * FK_;

    auto load_chunk = [&](int c) {
        uint32_t stb = sb + (c % 3) * STAGE;
        int k0 = c * 64;
#pragma unroll
        for (int u = tid; u < 1024; u += 256) {
            int row = u >> 3, sg = (u & 7) * 16;
            uint32_t off = SWZ(row * 128 + sg);
            cp16(stb + off, (const char*)(Ab + (size_t)row * FK_ + k0) + sg);
            cp16(stb + ASZ + off, (const char*)(Bb + (size_t)row * FK_ + k0) + sg);
        }
    };

    float acc[2][8][4];
#pragma unroll
    for (int mt = 0; mt < 2; mt++)
#pragma unroll
        for (int f = 0; f < 8; f++)
#pragma unroll
            for (int j = 0; j < 4; j++) acc[mt][f][j] = 0.0f;

    int aRow = warpM * 32 + (lane & 15);
    int aK8  = (lane >> 4);
    int bNr  = warpN * 64 + ((lane >> 4) << 3) + (lane & 7);
    int bK8  = (lane >> 3) & 1;

    load_chunk(0); CP_COMMIT();
    load_chunk(1); CP_COMMIT();

    for (int c = 0; c < NCHUNK; c++) {
        if (c + 1 < NCHUNK) { CP_WAIT(1); } else { CP_WAIT(0); }
        __syncthreads();
        if (c + 2 < NCHUNK) { load_chunk(c + 2); CP_COMMIT(); }
        uint32_t stb = sb + (c % 3) * STAGE;
#pragma unroll
        for (int kk = 0; kk < 4; kk++) {
            uint32_t a[2][4], b[4][4];
#pragma unroll
            for (int mt = 0; mt < 2; mt++) {
                int khalf = kk * 16 + aK8 * 8;
                ldm4(a[mt], stb + SWZ((aRow + mt * 16) * 128 + khalf * 2));
            }
#pragma unroll
            for (int np = 0; np < 4; np++) {
                int khalf = kk * 16 + bK8 * 8;
                ldm4(b[np], stb + ASZ + SWZ((bNr + np * 16) * 128 + khalf * 2));
            }
#pragma unroll
            for (int mt = 0; mt < 2; mt++)
#pragma unroll
                for (int np = 0; np < 4; np++) {
                    mma16816(acc[mt][np * 2 + 0], a[mt], &b[np][0]);
                    mma16816(acc[mt][np * 2 + 1], a[mt], &b[np][2]);
                }
        }
    }

    // epilogue
    int g = lane >> 2, t = lane & 3;
#pragma unroll
    for (int f = 0; f < 8; f++) {
        int col = bn + warpN * 64 + f * 8 + 2 * t;
        float2 bv = *(const float2*)(br + col);
#pragma unroll
        for (int mt = 0; mt < 2; mt++) {
            int r0 = warpM * 32 + mt * 16 + g;
            float* c0 = C + (bm + r0) * (size_t)ON_ + col;
            float* c1 = C + (bm + r0 + 8) * (size_t)ON_ + col;
            float2 v0 = { acc[mt][f][0] + bv.x, acc[mt][f][1] + bv.y };
            float2 v1 = { acc[mt][f][2] + bv.x, acc[mt][f][3] + bv.y };
            *(float2*)c0 = v0;
            *(float2*)c1 = v1;
        }
    }
}

// ---------------------------------------------------------------------------
extern "C" void kernel_launch(void* const* d_in, const int* in_sizes, int n_in,
                              void* d_out, int out_size)
{
    const float* x     = (const float*)d_in[0];
    const float* We    = (const float*)d_in[1];
    const float* be    = (const float*)d_in[2];
    const float* omega = (const float*)d_in[3];
    const float* Wr    = (const float*)d_in[4];
    const float* br    = (const float*)d_in[5];

    float* out     = (float*)d_out;
    float* logits  = out;                                   // [B,S,O]
    float* ph_hist = out + (size_t)MTOT_ * ON_;             // [B,S,H]
    float* wb_hist = ph_hist + (size_t)MTOT_ * HN_;         // [B,S,H]

    cudaFuncSetAttribute(gemm_hmma, cudaFuncAttributeMaxDynamicSharedMemorySize, GEMM_SMEM);

    encoder_kernel<<<MTOT_ / 256, 256>>>(x, We, be);
    rep_kernel<<<SN_ + (SN_ + 255) / 256, 256>>>(x);
    wconv<<<(ON_ * FK_ + 255) / 256, 256>>>(Wr);
    recur_state<<<(BN_ * HN_) / 128, 128>>>(omega, ph_hist, wb_hist);   // 4th launch -> profiled
    featurize<<<(MTOT_ * HN_ / 2) / 256, 256>>>(ph_hist, wb_hist);
    gemm_hmma<<<dim3(4, 1024), 256, GEMM_SMEM>>>(br, logits);
}

// round 14
// speedup vs baseline: 1.5970x; 1.1579x over previous
#include <cuda_runtime.h>
#include <cuda_bf16.h>
#include <cuda_fp16.h>
#include <math.h>
#include <stdint.h>

// Problem dims
#define BN_ 128
#define SN_ 1024
#define DN_ 64
#define HN_ 128
#define ON_ 512
#define FK_ 896
#define MTOT_ (BN_ * SN_)   // 131072

// ---------------------------------------------------------------------------
// Scratch (device globals: allocation-free rule)
// ---------------------------------------------------------------------------
__device__ float  g_pt[(size_t)MTOT_ * HN_];     // 64 MB encoded phases
__device__ __half g_f[(size_t)MTOT_ * FK_];      // 235 MB feats fp16
__device__ __half g_w[(size_t)ON_ * FK_];        // Wr fp16
__device__ int    g_rep[SN_];
__device__ float  g_swb[SN_];                    // 0.25*sin(nominal wb[t])

__device__ __forceinline__ uint32_t smem_u32(const void* p) {
    uint32_t a;
    asm("{ .reg .u64 t; cvta.to.shared.u64 t, %1; cvt.u32.u64 %0, t; }" : "=r"(a) : "l"(p));
    return a;
}
__device__ __forceinline__ void cp16(uint32_t dst, const void* src) {
    asm volatile("cp.async.cg.shared.global [%0], [%1], 16;" :: "r"(dst), "l"(src));
}
#define CP_COMMIT() asm volatile("cp.async.commit_group;" ::: "memory")
#define CP_WAIT(n)  asm volatile("cp.async.wait_group %0;" :: "n"(n) : "memory")
#define SWZ(o) ((o) ^ (((o) >> 3) & 0x70))

__device__ __forceinline__ void ldm4(uint32_t* r, uint32_t addr) {
    asm volatile("ldmatrix.sync.aligned.m8n8.x4.shared.b16 {%0,%1,%2,%3}, [%4];"
        : "=r"(r[0]), "=r"(r[1]), "=r"(r[2]), "=r"(r[3]) : "r"(addr));
}
__device__ __forceinline__ void mma16816(float* d, const uint32_t* a, const uint32_t* b) {
    asm volatile("mma.sync.aligned.m16n8k16.row.col.f32.f16.f16.f32 "
        "{%0,%1,%2,%3}, {%4,%5,%6,%7}, {%8,%9}, {%0,%1,%2,%3};"
        : "+f"(d[0]), "+f"(d[1]), "+f"(d[2]), "+f"(d[3])
        : "r"(a[0]), "r"(a[1]), "r"(a[2]), "r"(a[3]), "r"(b[0]), "r"(b[1]));
}

// ---------------------------------------------------------------------------
// Kernel 1: encoder. Thread-per-(b,s) row, x in 64 regs, We broadcast LDS.
// ---------------------------------------------------------------------------
__global__ __launch_bounds__(256) void encoder_kernel(
    const float* __restrict__ x, const float* __restrict__ We,
    const float* __restrict__ be)
{
    __shared__ float4 sWe[HN_ * (DN_ / 4)];   // 32 KB, [h][d4]
    __shared__ float  sbe[HN_];
    int tid = threadIdx.x;

    for (int i = tid; i < HN_ * (DN_ / 4); i += 256)
        sWe[i] = ((const float4*)We)[i];
    if (tid < HN_) sbe[tid] = be[tid];

    size_t m = (size_t)blockIdx.x * 256 + tid;    // (b,s) row id
    float4 xr[DN_ / 4];
    const float4* xp = (const float4*)(x + m * DN_);
#pragma unroll
    for (int i = 0; i < DN_ / 4; i++) xr[i] = xp[i];
    __syncthreads();

    float* out = g_pt + m * HN_;
#pragma unroll 2
    for (int h0 = 0; h0 < HN_; h0 += 4) {
        float4 accv;
        float* acc = (float*)&accv;
#pragma unroll
        for (int j = 0; j < 4; j++) {
            int h = h0 + j;
            float a = sbe[h];
            const float4* wrow = &sWe[h * (DN_ / 4)];
#pragma unroll
            for (int i = 0; i < DN_ / 4; i++) {
                float4 w = wrow[i];
                a += xr[i].x * w.x + xr[i].y * w.y + xr[i].z * w.z + xr[i].w * w.w;
            }
            acc[j] = a;
        }
        *(float4*)(out + h0) = accv;
    }
}

// ---------------------------------------------------------------------------
// Kernel 2: repeat flags (fast-path precheck) + nominal-wb sin table.
// ---------------------------------------------------------------------------
__global__ __launch_bounds__(256) void rep_kernel(const float* __restrict__ x)
{
    if (blockIdx.x >= SN_) {   // table blocks
        int t = (blockIdx.x - SN_) * 256 + threadIdx.x;
        if (t < SN_) g_swb[t] = 0.25f * __sinf((float)(t + 1) * 0.015625f);
        return;
    }
    int s = blockIdx.x;
    if (s == 0) { if (threadIdx.x == 0) g_rep[0] = 0; return; }
    __shared__ int fast;
    if (threadIdx.x == 0)
        fast = (x[(size_t)s * DN_] != x[(size_t)(s - 1) * DN_]);
    __syncthreads();
    if (fast) { if (threadIdx.x == 0) g_rep[s] = 0; return; }
    int ok = 1;
    for (int i = threadIdx.x; i < BN_ * DN_; i += 256) {
        int b = i >> 6, d = i & 63;
        size_t base = ((size_t)b * SN_ + s) * DN_ + d;
        if (x[base] != x[base - DN_]) ok = 0;
    }
    ok = __syncthreads_and(ok);
    if (threadIdx.x == 0) g_rep[s] = ok;
}

// ---------------------------------------------------------------------------
// Kernel 3: Wr -> fp16
// ---------------------------------------------------------------------------
__global__ __launch_bounds__(256) void wconv(const float* __restrict__ Wr)
{
    size_t i = (size_t)blockIdx.x * 256 + threadIdx.x;
    if (i < (size_t)ON_ * FK_) g_w[i] = __float2half(Wr[i]);
}

// ---------------------------------------------------------------------------
// Kernel 4: recurrence + featurize, fused. One CTA per batch b (128 CTAs,
// 128 thr = all h). pt staged through a 4-stage cp.async smem ring
// (4KB/stage = 8 steps), so the serial chain never waits on global loads.
// Unconditional CP_COMMIT keeps exactly 3 groups pending -> CP_WAIT(2)
// always completes stage blk; barrier covers cross-warp visibility + WAR.
// Pacing term: 7 MUFU ops/step x rt8 = ~56cy -> ~35us predicted.
// feats [M, 7H]: cos ph | sin ph | cos ph/2 | sin ph/2 | cos wb | sin wb | ph
// ---------------------------------------------------------------------------
#define RNST 4
__global__ __launch_bounds__(128) void recur_feat(
    const float* __restrict__ omega,
    float* __restrict__ ph_hist, float* __restrict__ wb_hist)
{
    __shared__ int   srep[SN_];
    __shared__ float sswb[SN_];
    __shared__ float spt[RNST][8 * HN_];     // 16 KB ring
    int tid = threadIdx.x;                   // = h
    int b = blockIdx.x;
    for (int i = tid; i < SN_; i += 128) { srep[i] = g_rep[i]; sswb[i] = g_swb[i]; }

    const float* pp = g_pt + (size_t)b * SN_ * HN_;
    uint32_t spt_b = smem_u32(&spt[0][0]);
    auto stage_load = [&](int blk) {
        uint32_t dst = spt_b + (blk & (RNST - 1)) * (8 * HN_ * 4);
        const char* src = (const char*)(pp + (size_t)blk * 8 * HN_);
        cp16(dst + tid * 16, src + (size_t)tid * 16);
        cp16(dst + 2048 + tid * 16, src + 2048 + (size_t)tid * 16);
    };
    stage_load(0); CP_COMMIT();
    stage_load(1); CP_COMMIT();
    stage_load(2); CP_COMMIT();
    __syncthreads();                          // srep/sswb ready

    float om = omega[tid];
    float ph = 0.0f, wb = 0.0f;
    bool diverged = false;                    // uniform (srep uniform)
    float* php = ph_hist + (size_t)b * SN_ * HN_ + tid;
    float* wbp = wb_hist + (size_t)b * SN_ * HN_ + tid;
    __half* fp = g_f + (size_t)b * SN_ * FK_ + tid;

    for (int blk = 0; blk < SN_ / 8; blk++) {
        CP_WAIT(2);
        __syncthreads();                      // stage blk visible; stage blk+3 free
        const float* sp = spt[blk & (RNST - 1)];
#pragma unroll
        for (int j = 0; j < 8; j++) {
            int t = blk * 8 + j;
            float p = sp[j * HN_ + tid];
            wb += 0.015625f;
            float swb = diverged ? 0.25f * __sinf(wb) : sswb[t];
            ph = ph + (om + swb) - __sinf(p - ph);
            if (srep[t]) { wb += 0.25f * __sinf(p - wb); diverged = true; }
            php[(size_t)t * HN_] = ph;
            wbp[(size_t)t * HN_] = wb;
            float c1, s1, c2, s2, c3, s3;
            __sincosf(ph, &s1, &c1);
            __sincosf(0.5f * ph, &s2, &c2);
            __sincosf(wb, &s3, &c3);
            __half* f = fp + (size_t)t * FK_;
            f[0 * HN_] = __float2half(c1);
            f[1 * HN_] = __float2half(s1);
            f[2 * HN_] = __float2half(c2);
            f[3 * HN_] = __float2half(s2);
            f[4 * HN_] = __float2half(c3);
            f[5 * HN_] = __float2half(s3);
            f[6 * HN_] = __float2half(ph);
        }
        if (blk + 3 < SN_ / 8) stage_load(blk + 3);
        CP_COMMIT();                          // unconditional: keeps 3 groups pending
    }
}

// ---------------------------------------------------------------------------
// Kernel 5: HMMA GEMM (unchanged: 278us measured, tensor=72%)
// ---------------------------------------------------------------------------
#define ASZ   16384
#define STAGE 32768
#define GEMM_SMEM (3 * STAGE + 1024)
#define NCHUNK 14

__global__ __launch_bounds__(256, 2) void gemm_hmma(
    const float* __restrict__ br, float* __restrict__ C)
{
    extern __shared__ char smem[];
    uint32_t sb = (smem_u32(smem) + 1023) & ~1023u;
    int tid = threadIdx.x;
    int lane = tid & 31, wid = tid >> 5;
    int warpM = wid & 3, warpN = wid >> 2;
    int bn = blockIdx.x * 128;                 // N tile (0..3)
    size_t bm = (size_t)blockIdx.y * 128;      // M tile

    const __half* Ab = g_f + bm * FK_;
    const __half* Bb = g_w + (size_t)bn * FK_;

    auto load_chunk = [&](int c) {
        uint32_t stb = sb + (c % 3) * STAGE;
        int k0 = c * 64;
#pragma unroll
        for (int u = tid; u < 1024; u += 256) {
            int row = u >> 3, sg = (u & 7) * 16;
            uint32_t off = SWZ(row * 128 + sg);
            cp16(stb + off, (const char*)(Ab + (size_t)row * FK_ + k0) + sg);
            cp16(stb + ASZ + off, (const char*)(Bb + (size_t)row * FK_ + k0) + sg);
        }
    };

    float acc[2][8][4];
#pragma unroll
    for (int mt = 0; mt < 2; mt++)
#pragma unroll
        for (int f = 0; f < 8; f++)
#pragma unroll
            for (int j = 0; j < 4; j++) acc[mt][f][j] = 0.0f;

    int aRow = warpM * 32 + (lane & 15);
    int aK8  = (lane >> 4);
    int bNr  = warpN * 64 + ((lane >> 4) << 3) + (lane & 7);
    int bK8  = (lane >> 3) & 1;

    load_chunk(0); CP_COMMIT();
    load_chunk(1); CP_COMMIT();

    for (int c = 0; c < NCHUNK; c++) {
        if (c + 1 < NCHUNK) { CP_WAIT(1); } else { CP_WAIT(0); }
        __syncthreads();
        if (c + 2 < NCHUNK) { load_chunk(c + 2); CP_COMMIT(); }
        uint32_t stb = sb + (c % 3) * STAGE;
#pragma unroll
        for (int kk = 0; kk < 4; kk++) {
            uint32_t a[2][4], b[4][4];
#pragma unroll
            for (int mt = 0; mt < 2; mt++) {
                int khalf = kk * 16 + aK8 * 8;
                ldm4(a[mt], stb + SWZ((aRow + mt * 16) * 128 + khalf * 2));
            }
#pragma unroll
            for (int np = 0; np < 4; np++) {
                int khalf = kk * 16 + bK8 * 8;
                ldm4(b[np], stb + ASZ + SWZ((bNr + np * 16) * 128 + khalf * 2));
            }
#pragma unroll
            for (int mt = 0; mt < 2; mt++)
#pragma unroll
                for (int np = 0; np < 4; np++) {
                    mma16816(acc[mt][np * 2 + 0], a[mt], &b[np][0]);
                    mma16816(acc[mt][np * 2 + 1], a[mt], &b[np][2]);
                }
        }
    }

    // epilogue
    int g = lane >> 2, t = lane & 3;
#pragma unroll
    for (int f = 0; f < 8; f++) {
        int col = bn + warpN * 64 + f * 8 + 2 * t;
        float2 bv = *(const float2*)(br + col);
#pragma unroll
        for (int mt = 0; mt < 2; mt++) {
            int r0 = warpM * 32 + mt * 16 + g;
            float* c0 = C + (bm + r0) * (size_t)ON_ + col;
            float* c1 = C + (bm + r0 + 8) * (size_t)ON_ + col;
            float2 v0 = { acc[mt][f][0] + bv.x, acc[mt][f][1] + bv.y };
            float2 v1 = { acc[mt][f][2] + bv.x, acc[mt][f][3] + bv.y };
            *(float2*)c0 = v0;
            *(float2*)c1 = v1;
        }
    }
}

// ---------------------------------------------------------------------------
extern "C" void kernel_launch(void* const* d_in, const int* in_sizes, int n_in,
                              void* d_out, int out_size)
{
    const float* x     = (const float*)d_in[0];
    const float* We    = (const float*)d_in[1];
    const float* be    = (const float*)d_in[2];
    const float* omega = (const float*)d_in[3];
    const float* Wr    = (const float*)d_in[4];
    const float* br    = (const float*)d_in[5];

    float* out     = (float*)d_out;
    float* logits  = out;                                   // [B,S,O]
    float* ph_hist = out + (size_t)MTOT_ * ON_;             // [B,S,H]
    float* wb_hist = ph_hist + (size_t)MTOT_ * HN_;         // [B,S,H]

    cudaFuncSetAttribute(gemm_hmma, cudaFuncAttributeMaxDynamicSharedMemorySize, GEMM_SMEM);

    encoder_kernel<<<MTOT_ / 256, 256>>>(x, We, be);
    rep_kernel<<<SN_ + (SN_ + 255) / 256, 256>>>(x);
    wconv<<<(ON_ * FK_ + 255) / 256, 256>>>(Wr);
    recur_feat<<<BN_, 128>>>(omega, ph_hist, wb_hist);      // 4th launch -> profiled
    gemm_hmma<<<dim3(4, 1024), 256, GEMM_SMEM>>>(br, logits);
}

// round 15
// speedup vs baseline: 1.6156x; 1.0116x over previous
#include <cuda_runtime.h>
#include <cuda_bf16.h>
#include <cuda_fp16.h>
#include <math.h>
#include <stdint.h>

// Problem dims
#define BN_ 128
#define SN_ 1024
#define DN_ 64
#define HN_ 128
#define ON_ 512
#define FK_ 896
#define MTOT_ (BN_ * SN_)   // 131072

// ---------------------------------------------------------------------------
// Scratch (device globals: allocation-free rule)
// ---------------------------------------------------------------------------
__device__ float  g_pt[(size_t)MTOT_ * HN_];     // 64 MB encoded phases
__device__ __half g_f[(size_t)MTOT_ * FK_];      // 235 MB feats fp16
__device__ __half g_w[(size_t)ON_ * FK_];        // Wr fp16
__device__ int    g_rep[SN_];
__device__ float  g_swb[SN_];                    // 0.25*sin(nominal wb[t])  (drive)
__device__ float  g_cwbt[SN_];                   // cos(nominal wb[t])       (feature)
__device__ float  g_swbt[SN_];                   // sin(nominal wb[t])       (feature)

__device__ __forceinline__ uint32_t smem_u32(const void* p) {
    uint32_t a;
    asm("{ .reg .u64 t; cvta.to.shared.u64 t, %1; cvt.u32.u64 %0, t; }" : "=r"(a) : "l"(p));
    return a;
}
__device__ __forceinline__ void cp16(uint32_t dst, const void* src) {
    asm volatile("cp.async.cg.shared.global [%0], [%1], 16;" :: "r"(dst), "l"(src));
}
#define CP_COMMIT() asm volatile("cp.async.commit_group;" ::: "memory")
#define CP_WAIT(n)  asm volatile("cp.async.wait_group %0;" :: "n"(n) : "memory")
#define SWZ(o) ((o) ^ (((o) >> 3) & 0x70))

__device__ __forceinline__ void ldm4(uint32_t* r, uint32_t addr) {
    asm volatile("ldmatrix.sync.aligned.m8n8.x4.shared.b16 {%0,%1,%2,%3}, [%4];"
        : "=r"(r[0]), "=r"(r[1]), "=r"(r[2]), "=r"(r[3]) : "r"(addr));
}
__device__ __forceinline__ void mma16816(float* d, const uint32_t* a, const uint32_t* b) {
    asm volatile("mma.sync.aligned.m16n8k16.row.col.f32.f16.f16.f32 "
        "{%0,%1,%2,%3}, {%4,%5,%6,%7}, {%8,%9}, {%0,%1,%2,%3};"
        : "+f"(d[0]), "+f"(d[1]), "+f"(d[2]), "+f"(d[3])
        : "r"(a[0]), "r"(a[1]), "r"(a[2]), "r"(a[3]), "r"(b[0]), "r"(b[1]));
}

// ---------------------------------------------------------------------------
// Kernel 1: encoder. Thread-per-(b,s) row, x in 64 regs, We broadcast LDS.
// ---------------------------------------------------------------------------
__global__ __launch_bounds__(256) void encoder_kernel(
    const float* __restrict__ x, const float* __restrict__ We,
    const float* __restrict__ be)
{
    __shared__ float4 sWe[HN_ * (DN_ / 4)];   // 32 KB, [h][d4]
    __shared__ float  sbe[HN_];
    int tid = threadIdx.x;

    for (int i = tid; i < HN_ * (DN_ / 4); i += 256)
        sWe[i] = ((const float4*)We)[i];
    if (tid < HN_) sbe[tid] = be[tid];

    size_t m = (size_t)blockIdx.x * 256 + tid;    // (b,s) row id
    float4 xr[DN_ / 4];
    const float4* xp = (const float4*)(x + m * DN_);
#pragma unroll
    for (int i = 0; i < DN_ / 4; i++) xr[i] = xp[i];
    __syncthreads();

    float* out = g_pt + m * HN_;
#pragma unroll 2
    for (int h0 = 0; h0 < HN_; h0 += 4) {
        float4 accv;
        float* acc = (float*)&accv;
#pragma unroll
        for (int j = 0; j < 4; j++) {
            int h = h0 + j;
            float a = sbe[h];
            const float4* wrow = &sWe[h * (DN_ / 4)];
#pragma unroll
            for (int i = 0; i < DN_ / 4; i++) {
                float4 w = wrow[i];
                a += xr[i].x * w.x + xr[i].y * w.y + xr[i].z * w.z + xr[i].w * w.w;
            }
            acc[j] = a;
        }
        *(float4*)(out + h0) = accv;
    }
}

// ---------------------------------------------------------------------------
// Kernel 2: repeat flags + wb tables + Wr->fp16, one launch (blockIdx split).
// Nominal wb[t] = (t+1)*2^-6 is EXACT in fp32, so the drive AND feature
// trig of wb are chain-independent until a repeat occurs.
// ---------------------------------------------------------------------------
#define TBL_BLOCKS ((SN_ + 255) / 256)
#define WCONV_BLOCKS ((ON_ * FK_ + 255) / 256)
__global__ __launch_bounds__(256) void prep_kernel(
    const float* __restrict__ x, const float* __restrict__ Wr)
{
    if (blockIdx.x < SN_) {
        int s = blockIdx.x;
        if (s == 0) { if (threadIdx.x == 0) g_rep[0] = 0; return; }
        __shared__ int fast;
        if (threadIdx.x == 0)
            fast = (x[(size_t)s * DN_] != x[(size_t)(s - 1) * DN_]);
        __syncthreads();
        if (fast) { if (threadIdx.x == 0) g_rep[s] = 0; return; }
        int ok = 1;
        for (int i = threadIdx.x; i < BN_ * DN_; i += 256) {
            int b = i >> 6, d = i & 63;
            size_t base = ((size_t)b * SN_ + s) * DN_ + d;
            if (x[base] != x[base - DN_]) ok = 0;
        }
        ok = __syncthreads_and(ok);
        if (threadIdx.x == 0) g_rep[s] = ok;
    } else if (blockIdx.x < SN_ + TBL_BLOCKS) {
        int t = (blockIdx.x - SN_) * 256 + threadIdx.x;
        if (t < SN_) {
            float wb = (float)(t + 1) * 0.015625f;
            float c, s;
            __sincosf(wb, &s, &c);
            g_swb[t]  = 0.25f * s;
            g_cwbt[t] = c;
            g_swbt[t] = s;
        }
    } else {
        size_t i = (size_t)(blockIdx.x - SN_ - TBL_BLOCKS) * 256 + threadIdx.x;
        if (i < (size_t)ON_ * FK_) g_w[i] = __float2half(Wr[i]);
    }
}

// ---------------------------------------------------------------------------
// Kernel 3: recurrence + featurize, fused. One CTA per batch b, 128 thr = h.
// pt staged via 4-stage cp.async ring. Fast path per step: __sinf(p-ph)
// [2 MUFU ops] + __sincosf(0.5ph) [3 ops] = 5 MUFU-pipe ops (~40cy); cos/sin
// of ph derived by half-angle FMAs; wb features from tables until diverged.
// feats [M, 7H]: cos ph | sin ph | cos ph/2 | sin ph/2 | cos wb | sin wb | ph
// ---------------------------------------------------------------------------
#define RNST 4
__global__ __launch_bounds__(128) void recur_feat(
    const float* __restrict__ omega,
    float* __restrict__ ph_hist, float* __restrict__ wb_hist)
{
    __shared__ int   srep[SN_];
    __shared__ float sswb[SN_];
    __shared__ float scwb[SN_];
    __shared__ float sswbt[SN_];
    __shared__ float spt[RNST][8 * HN_];     // 16 KB ring
    int tid = threadIdx.x;                   // = h
    int b = blockIdx.x;
    for (int i = tid; i < SN_; i += 128) {
        srep[i] = g_rep[i];
        sswb[i] = g_swb[i];
        scwb[i] = g_cwbt[i];
        sswbt[i] = g_swbt[i];
    }

    const float* pp = g_pt + (size_t)b * SN_ * HN_;
    uint32_t spt_b = smem_u32(&spt[0][0]);
    auto stage_load = [&](int blk) {
        uint32_t dst = spt_b + (blk & (RNST - 1)) * (8 * HN_ * 4);
        const char* src = (const char*)(pp + (size_t)blk * 8 * HN_);
        cp16(dst + tid * 16, src + (size_t)tid * 16);
        cp16(dst + 2048 + tid * 16, src + 2048 + (size_t)tid * 16);
    };
    stage_load(0); CP_COMMIT();
    stage_load(1); CP_COMMIT();
    stage_load(2); CP_COMMIT();
    __syncthreads();                          // tables ready

    float om = omega[tid];
    float ph = 0.0f, wb = 0.0f;
    bool diverged = false;                    // uniform (srep uniform)
    float* php = ph_hist + (size_t)b * SN_ * HN_ + tid;
    float* wbp = wb_hist + (size_t)b * SN_ * HN_ + tid;
    __half* fp = g_f + (size_t)b * SN_ * FK_ + tid;

    for (int blk = 0; blk < SN_ / 8; blk++) {
        CP_WAIT(2);
        __syncthreads();                      // stage blk visible; stage blk+3 free
        const float* sp = spt[blk & (RNST - 1)];
#pragma unroll
        for (int j = 0; j < 8; j++) {
            int t = blk * 8 + j;
            float p = sp[j * HN_ + tid];
            wb += 0.015625f;
            float swb = diverged ? 0.25f * __sinf(wb) : sswb[t];
            ph = ph + (om + swb) - __sinf(p - ph);
            if (srep[t]) { wb += 0.25f * __sinf(p - wb); diverged = true; }
            php[(size_t)t * HN_] = ph;
            wbp[(size_t)t * HN_] = wb;
            float c2, s2;
            __sincosf(0.5f * ph, &s2, &c2);
            float c1 = fmaf(2.0f * c2, c2, -1.0f);   // cos(ph)
            float s1 = 2.0f * s2 * c2;               // sin(ph)
            float c3, s3;
            if (diverged) { __sincosf(wb, &s3, &c3); }
            else          { c3 = scwb[t]; s3 = sswbt[t]; }
            __half* f = fp + (size_t)t * FK_;
            f[0 * HN_] = __float2half(c1);
            f[1 * HN_] = __float2half(s1);
            f[2 * HN_] = __float2half(c2);
            f[3 * HN_] = __float2half(s2);
            f[4 * HN_] = __float2half(c3);
            f[5 * HN_] = __float2half(s3);
            f[6 * HN_] = __float2half(ph);
        }
        if (blk + 3 < SN_ / 8) stage_load(blk + 3);
        CP_COMMIT();                          // unconditional: keeps 3 groups pending
    }
}

// ---------------------------------------------------------------------------
// Kernel 4: HMMA GEMM (unchanged: 278us measured, tensor=72%).
// Now the 4th launch -> gets profiled next round.
// ---------------------------------------------------------------------------
#define ASZ   16384
#define STAGE 32768
#define GEMM_SMEM (3 * STAGE + 1024)
#define NCHUNK 14

__global__ __launch_bounds__(256, 2) void gemm_hmma(
    const float* __restrict__ br, float* __restrict__ C)
{
    extern __shared__ char smem[];
    uint32_t sb = (smem_u32(smem) + 1023) & ~1023u;
    int tid = threadIdx.x;
    int lane = tid & 31, wid = tid >> 5;
    int warpM = wid & 3, warpN = wid >> 2;
    int bn = blockIdx.x * 128;                 // N tile (0..3)
    size_t bm = (size_t)blockIdx.y * 128;      // M tile

    const __half* Ab = g_f + bm * FK_;
    const __half* Bb = g_w + (size_t)bn * FK_;

    auto load_chunk = [&](int c) {
        uint32_t stb = sb + (c % 3) * STAGE;
        int k0 = c * 64;
#pragma unroll
        for (int u = tid; u < 1024; u += 256) {
            int row = u >> 3, sg = (u & 7) * 16;
            uint32_t off = SWZ(row * 128 + sg);
            cp16(stb + off, (const char*)(Ab + (size_t)row * FK_ + k0) + sg);
            cp16(stb + ASZ + off, (const char*)(Bb + (size_t)row * FK_ + k0) + sg);
        }
    };

    float acc[2][8][4];
#pragma unroll
    for (int mt = 0; mt < 2; mt++)
#pragma unroll
        for (int f = 0; f < 8; f++)
#pragma unroll
            for (int j = 0; j < 4; j++) acc[mt][f][j] = 0.0f;

    int aRow = warpM * 32 + (lane & 15);
    int aK8  = (lane >> 4);
    int bNr  = warpN * 64 + ((lane >> 4) << 3) + (lane & 7);
    int bK8  = (lane >> 3) & 1;

    load_chunk(0); CP_COMMIT();
    load_chunk(1); CP_COMMIT();

    for (int c = 0; c < NCHUNK; c++) {
        if (c + 1 < NCHUNK) { CP_WAIT(1); } else { CP_WAIT(0); }
        __syncthreads();
        if (c + 2 < NCHUNK) { load_chunk(c + 2); CP_COMMIT(); }
        uint32_t stb = sb + (c % 3) * STAGE;
#pragma unroll
        for (int kk = 0; kk < 4; kk++) {
            uint32_t a[2][4], b[4][4];
#pragma unroll
            for (int mt = 0; mt < 2; mt++) {
                int khalf = kk * 16 + aK8 * 8;
                ldm4(a[mt], stb + SWZ((aRow + mt * 16) * 128 + khalf * 2));
            }
#pragma unroll
            for (int np = 0; np < 4; np++) {
                int khalf = kk * 16 + bK8 * 8;
                ldm4(b[np], stb + ASZ + SWZ((bNr + np * 16) * 128 + khalf * 2));
            }
#pragma unroll
            for (int mt = 0; mt < 2; mt++)
#pragma unroll
                for (int np = 0; np < 4; np++) {
                    mma16816(acc[mt][np * 2 + 0], a[mt], &b[np][0]);
                    mma16816(acc[mt][np * 2 + 1], a[mt], &b[np][2]);
                }
        }
    }

    // epilogue
    int g = lane >> 2, t = lane & 3;
#pragma unroll
    for (int f = 0; f < 8; f++) {
        int col = bn + warpN * 64 + f * 8 + 2 * t;
        float2 bv = *(const float2*)(br + col);
#pragma unroll
        for (int mt = 0; mt < 2; mt++) {
            int r0 = warpM * 32 + mt * 16 + g;
            float* c0 = C + (bm + r0) * (size_t)ON_ + col;
            float* c1 = C + (bm + r0 + 8) * (size_t)ON_ + col;
            float2 v0 = { acc[mt][f][0] + bv.x, acc[mt][f][1] + bv.y };
            float2 v1 = { acc[mt][f][2] + bv.x, acc[mt][f][3] + bv.y };
            *(float2*)c0 = v0;
            *(float2*)c1 = v1;
        }
    }
}

// ---------------------------------------------------------------------------
extern "C" void kernel_launch(void* const* d_in, const int* in_sizes, int n_in,
                              void* d_out, int out_size)
{
    const float* x     = (const float*)d_in[0];
    const float* We    = (const float*)d_in[1];
    const float* be    = (const float*)d_in[2];
    const float* omega = (const float*)d_in[3];
    const float* Wr    = (const float*)d_in[4];
    const float* br    = (const float*)d_in[5];

    float* out     = (float*)d_out;
    float* logits  = out;                                   // [B,S,O]
    float* ph_hist = out + (size_t)MTOT_ * ON_;             // [B,S,H]
    float* wb_hist = ph_hist + (size_t)MTOT_ * HN_;         // [B,S,H]

    cudaFuncSetAttribute(gemm_hmma, cudaFuncAttributeMaxDynamicSharedMemorySize, GEMM_SMEM);

    encoder_kernel<<<MTOT_ / 256, 256>>>(x, We, be);
    prep_kernel<<<SN_ + TBL_BLOCKS + WCONV_BLOCKS, 256>>>(x, Wr);
    recur_feat<<<BN_, 128>>>(omega, ph_hist, wb_hist);
    gemm_hmma<<<dim3(4, 1024), 256, GEMM_SMEM>>>(br, logits);   // 4th launch -> profiled
}

// round 17
// speedup vs baseline: 1.6246x; 1.0056x over previous
#include <cuda_runtime.h>
#include <cuda_bf16.h>
#include <cuda_fp16.h>
#include <math.h>
#include <stdint.h>

// Problem dims
#define BN_ 128
#define SN_ 1024
#define DN_ 64
#define HN_ 128
#define ON_ 512
#define FK_ 896
#define MTOT_ (BN_ * SN_)   // 131072

// ---------------------------------------------------------------------------
// Scratch (device globals: allocation-free rule)
// ---------------------------------------------------------------------------
__device__ float  g_pt[(size_t)MTOT_ * HN_];     // 64 MB encoded phases
__device__ __half g_f[(size_t)MTOT_ * FK_];      // 235 MB feats fp16
__device__ __half g_w[(size_t)ON_ * FK_];        // Wr fp16
__device__ int    g_rep[SN_];
__device__ float  g_swb[SN_];                    // 0.25*sin(nominal wb[t])  (drive)
__device__ float  g_cwbt[SN_];                   // cos(nominal wb[t])       (feature)
__device__ float  g_swbt[SN_];                   // sin(nominal wb[t])       (feature)

__device__ __forceinline__ uint32_t smem_u32(const void* p) {
    uint32_t a;
    asm("{ .reg .u64 t; cvta.to.shared.u64 t, %1; cvt.u32.u64 %0, t; }" : "=r"(a) : "l"(p));
    return a;
}
__device__ __forceinline__ void cp16(uint32_t dst, const void* src) {
    asm volatile("cp.async.cg.shared.global [%0], [%1], 16;" :: "r"(dst), "l"(src));
}
#define CP_COMMIT() asm volatile("cp.async.commit_group;" ::: "memory")
#define CP_WAIT(n)  asm volatile("cp.async.wait_group %0;" :: "n"(n) : "memory")
#define SWZ(o) ((o) ^ (((o) >> 3) & 0x70))

__device__ __forceinline__ void ldm4(uint32_t* r, uint32_t addr) {
    asm volatile("ldmatrix.sync.aligned.m8n8.x4.shared.b16 {%0,%1,%2,%3}, [%4];"
        : "=r"(r[0]), "=r"(r[1]), "=r"(r[2]), "=r"(r[3]) : "r"(addr));
}
__device__ __forceinline__ void mma16816(float* d, const uint32_t* a, const uint32_t* b) {
    asm volatile("mma.sync.aligned.m16n8k16.row.col.f32.f16.f16.f32 "
        "{%0,%1,%2,%3}, {%4,%5,%6,%7}, {%8,%9}, {%0,%1,%2,%3};"
        : "+f"(d[0]), "+f"(d[1]), "+f"(d[2]), "+f"(d[3])
        : "r"(a[0]), "r"(a[1]), "r"(a[2]), "r"(a[3]), "r"(b[0]), "r"(b[1]));
}

// ---------------------------------------------------------------------------
// Kernel 1: encoder (fp32 exact — the recurrence amplifies pt noise ~30x, so
// pt needs <=3e-6 accuracy; bf16-split proved fatal in R16) MERGED with
// prep work (repeat flags, wb tables, Wr->fp16) via blockIdx range split.
// Independent work: prep blocks pack into the same wave as encoder blocks.
// ---------------------------------------------------------------------------
#define ENC_BLOCKS   (MTOT_ / 256)                  // 512
#define TBL_BLOCKS   ((SN_ + 255) / 256)            // 4
#define WCONV_BLOCKS ((ON_ * FK_ + 255) / 256)      // 1792
#define TOTAL_BLOCKS (ENC_BLOCKS + SN_ + TBL_BLOCKS + WCONV_BLOCKS)

__global__ __launch_bounds__(256) void enc_prep_kernel(
    const float* __restrict__ x, const float* __restrict__ We,
    const float* __restrict__ be, const float* __restrict__ Wr)
{
    __shared__ float4 sWe[HN_ * (DN_ / 4)];   // 32 KB, [h][d4]
    __shared__ float  sbe[HN_];
    int tid = threadIdx.x;

    if (blockIdx.x < ENC_BLOCKS) {
        // ---- encoder: thread-per-(b,s) row, x in 64 regs, We broadcast LDS
        for (int i = tid; i < HN_ * (DN_ / 4); i += 256)
            sWe[i] = ((const float4*)We)[i];
        if (tid < HN_) sbe[tid] = be[tid];

        size_t m = (size_t)blockIdx.x * 256 + tid;    // (b,s) row id
        float4 xr[DN_ / 4];
        const float4* xp = (const float4*)(x + m * DN_);
#pragma unroll
        for (int i = 0; i < DN_ / 4; i++) xr[i] = xp[i];
        __syncthreads();

        float* out = g_pt + m * HN_;
#pragma unroll 2
        for (int h0 = 0; h0 < HN_; h0 += 4) {
            float4 accv;
            float* acc = (float*)&accv;
#pragma unroll
            for (int j = 0; j < 4; j++) {
                int h = h0 + j;
                float a = sbe[h];
                const float4* wrow = &sWe[h * (DN_ / 4)];
#pragma unroll
                for (int i = 0; i < DN_ / 4; i++) {
                    float4 w = wrow[i];
                    a += xr[i].x * w.x + xr[i].y * w.y + xr[i].z * w.z + xr[i].w * w.w;
                }
                acc[j] = a;
            }
            *(float4*)(out + h0) = accv;
        }
    } else if (blockIdx.x < ENC_BLOCKS + SN_) {
        // ---- repeat flags (fast-path single-element precheck)
        int s = blockIdx.x - ENC_BLOCKS;
        if (s == 0) { if (tid == 0) g_rep[0] = 0; return; }
        __shared__ int fast;
        if (tid == 0)
            fast = (x[(size_t)s * DN_] != x[(size_t)(s - 1) * DN_]);
        __syncthreads();
        if (fast) { if (tid == 0) g_rep[s] = 0; return; }
        int ok = 1;
        for (int i = tid; i < BN_ * DN_; i += 256) {
            int b = i >> 6, d = i & 63;
            size_t base = ((size_t)b * SN_ + s) * DN_ + d;
            if (x[base] != x[base - DN_]) ok = 0;
        }
        ok = __syncthreads_and(ok);
        if (tid == 0) g_rep[s] = ok;
    } else if (blockIdx.x < ENC_BLOCKS + SN_ + TBL_BLOCKS) {
        // ---- wb tables: nominal wb[t]=(t+1)*2^-6 is exact in fp32
        int t = (blockIdx.x - ENC_BLOCKS - SN_) * 256 + tid;
        if (t < SN_) {
            float wb = (float)(t + 1) * 0.015625f;
            float c, s;
            __sincosf(wb, &s, &c);
            g_swb[t]  = 0.25f * s;
            g_cwbt[t] = c;
            g_swbt[t] = s;
        }
    } else {
        // ---- Wr -> fp16
        size_t i = (size_t)(blockIdx.x - ENC_BLOCKS - SN_ - TBL_BLOCKS) * 256 + tid;
        if (i < (size_t)ON_ * FK_) g_w[i] = __float2half(Wr[i]);
    }
}

// ---------------------------------------------------------------------------
// Kernel 2: recurrence + featurize, fused (measured ~84us).
// feats [M, 7H]: cos ph | sin ph | cos ph/2 | sin ph/2 | cos wb | sin wb | ph
// ---------------------------------------------------------------------------
#define RNST 4
__global__ __launch_bounds__(128) void recur_feat(
    const float* __restrict__ omega,
    float* __restrict__ ph_hist, float* __restrict__ wb_hist)
{
    __shared__ int   srep[SN_];
    __shared__ float sswb[SN_];
    __shared__ float scwb[SN_];
    __shared__ float sswbt[SN_];
    __shared__ float spt[RNST][8 * HN_];     // 16 KB ring
    int tid = threadIdx.x;                   // = h
    int b = blockIdx.x;
    for (int i = tid; i < SN_; i += 128) {
        srep[i] = g_rep[i];
        sswb[i] = g_swb[i];
        scwb[i] = g_cwbt[i];
        sswbt[i] = g_swbt[i];
    }

    const float* pp = g_pt + (size_t)b * SN_ * HN_;
    uint32_t spt_b = smem_u32(&spt[0][0]);
    auto stage_load = [&](int blk) {
        uint32_t dst = spt_b + (blk & (RNST - 1)) * (8 * HN_ * 4);
        const char* src = (const char*)(pp + (size_t)blk * 8 * HN_);
        cp16(dst + tid * 16, src + (size_t)tid * 16);
        cp16(dst + 2048 + tid * 16, src + 2048 + (size_t)tid * 16);
    };
    stage_load(0); CP_COMMIT();
    stage_load(1); CP_COMMIT();
    stage_load(2); CP_COMMIT();
    __syncthreads();                          // tables ready

    float om = omega[tid];
    float ph = 0.0f, wb = 0.0f;
    bool diverged = false;                    // uniform (srep uniform)
    float* php = ph_hist + (size_t)b * SN_ * HN_ + tid;
    float* wbp = wb_hist + (size_t)b * SN_ * HN_ + tid;
    __half* fp = g_f + (size_t)b * SN_ * FK_ + tid;

    for (int blk = 0; blk < SN_ / 8; blk++) {
        CP_WAIT(2);
        __syncthreads();                      // stage blk visible; stage blk+3 free
        const float* sp = spt[blk & (RNST - 1)];
#pragma unroll
        for (int j = 0; j < 8; j++) {
            int t = blk * 8 + j;
            float p = sp[j * HN_ + tid];
            wb += 0.015625f;
            float swb = diverged ? 0.25f * __sinf(wb) : sswb[t];
            ph = ph + (om + swb) - __sinf(p - ph);
            if (srep[t]) { wb += 0.25f * __sinf(p - wb); diverged = true; }
            php[(size_t)t * HN_] = ph;
            wbp[(size_t)t * HN_] = wb;
            float c2, s2;
            __sincosf(0.5f * ph, &s2, &c2);
            float c1 = fmaf(2.0f * c2, c2, -1.0f);   // cos(ph)
            float s1 = 2.0f * s2 * c2;               // sin(ph)
            float c3, s3;
            if (diverged) { __sincosf(wb, &s3, &c3); }
            else          { c3 = scwb[t]; s3 = sswbt[t]; }
            __half* f = fp + (size_t)t * FK_;
            f[0 * HN_] = __float2half(c1);
            f[1 * HN_] = __float2half(s1);
            f[2 * HN_] = __float2half(c2);
            f[3 * HN_] = __float2half(s2);
            f[4 * HN_] = __float2half(c3);
            f[5 * HN_] = __float2half(s3);
            f[6 * HN_] = __float2half(ph);
        }
        if (blk + 3 < SN_ / 8) stage_load(blk + 3);
        CP_COMMIT();                          // unconditional: keeps 3 groups pending
    }
}

// ---------------------------------------------------------------------------
// Kernel 3: HMMA GEMM (unchanged: 275us measured, tensor=72%)
// ---------------------------------------------------------------------------
#define ASZ   16384
#define STAGE 32768
#define GEMM_SMEM (3 * STAGE + 1024)
#define NCHUNK 14

__global__ __launch_bounds__(256, 2) void gemm_hmma(
    const float* __restrict__ br, float* __restrict__ C)
{
    extern __shared__ char smem[];
    uint32_t sb = (smem_u32(smem) + 1023) & ~1023u;
    int tid = threadIdx.x;
    int lane = tid & 31, wid = tid >> 5;
    int warpM = wid & 3, warpN = wid >> 2;
    int bn = blockIdx.x * 128;                 // N tile (0..3)
    size_t bm = (size_t)blockIdx.y * 128;      // M tile

    const __half* Ab = g_f + bm * FK_;
    const __half* Bb = g_w + (size_t)bn * FK_;

    auto load_chunk = [&](int c) {
        uint32_t stb = sb + (c % 3) * STAGE;
        int k0 = c * 64;
#pragma unroll
        for (int u = tid; u < 1024; u += 256) {
            int row = u >> 3, sg = (u & 7) * 16;
            uint32_t off = SWZ(row * 128 + sg);
            cp16(stb + off, (const char*)(Ab + (size_t)row * FK_ + k0) + sg);
            cp16(stb + ASZ + off, (const char*)(Bb + (size_t)row * FK_ + k0) + sg);
        }
    };

    float acc[2][8][4];
#pragma unroll
    for (int mt = 0; mt < 2; mt++)
#pragma unroll
        for (int f = 0; f < 8; f++)
#pragma unroll
            for (int j = 0; j < 4; j++) acc[mt][f][j] = 0.0f;

    int aRow = warpM * 32 + (lane & 15);
    int aK8  = (lane >> 4);
    int bNr  = warpN * 64 + ((lane >> 4) << 3) + (lane & 7);
    int bK8  = (lane >> 3) & 1;

    load_chunk(0); CP_COMMIT();
    load_chunk(1); CP_COMMIT();

    for (int c = 0; c < NCHUNK; c++) {
        if (c + 1 < NCHUNK) { CP_WAIT(1); } else { CP_WAIT(0); }
        __syncthreads();
        if (c + 2 < NCHUNK) { load_chunk(c + 2); CP_COMMIT(); }
        uint32_t stb = sb + (c % 3) * STAGE;
#pragma unroll
        for (int kk = 0; kk < 4; kk++) {
            uint32_t a[2][4], b[4][4];
#pragma unroll
            for (int mt = 0; mt < 2; mt++) {
                int khalf = kk * 16 + aK8 * 8;
                ldm4(a[mt], stb + SWZ((aRow + mt * 16) * 128 + khalf * 2));
            }
#pragma unroll
            for (int np = 0; np < 4; np++) {
                int khalf = kk * 16 + bK8 * 8;
                ldm4(b[np], stb + ASZ + SWZ((bNr + np * 16) * 128 + khalf * 2));
            }
#pragma unroll
            for (int mt = 0; mt < 2; mt++)
#pragma unroll
                for (int np = 0; np < 4; np++) {
                    mma16816(acc[mt][np * 2 + 0], a[mt], &b[np][0]);
                    mma16816(acc[mt][np * 2 + 1], a[mt], &b[np][2]);
                }
        }
    }

    // epilogue
    int g = lane >> 2, t = lane & 3;
#pragma unroll
    for (int f = 0; f < 8; f++) {
        int col = bn + warpN * 64 + f * 8 + 2 * t;
        float2 bv = *(const float2*)(br + col);
#pragma unroll
        for (int mt = 0; mt < 2; mt++) {
            int r0 = warpM * 32 + mt * 16 + g;
            float* c0 = C + (bm + r0) * (size_t)ON_ + col;
            float* c1 = C + (bm + r0 + 8) * (size_t)ON_ + col;
            float2 v0 = { acc[mt][f][0] + bv.x, acc[mt][f][1] + bv.y };
            float2 v1 = { acc[mt][f][2] + bv.x, acc[mt][f][3] + bv.y };
            *(float2*)c0 = v0;
            *(float2*)c1 = v1;
        }
    }
}

// ---------------------------------------------------------------------------
extern "C" void kernel_launch(void* const* d_in, const int* in_sizes, int n_in,
                              void* d_out, int out_size)
{
    const float* x     = (const float*)d_in[0];
    const float* We    = (const float*)d_in[1];
    const float* be    = (const float*)d_in[2];
    const float* omega = (const float*)d_in[3];
    const float* Wr    = (const float*)d_in[4];
    const float* br    = (const float*)d_in[5];

    float* out     = (float*)d_out;
    float* logits  = out;                                   // [B,S,O]
    float* ph_hist = out + (size_t)MTOT_ * ON_;             // [B,S,H]
    float* wb_hist = ph_hist + (size_t)MTOT_ * HN_;         // [B,S,H]

    cudaFuncSetAttribute(gemm_hmma, cudaFuncAttributeMaxDynamicSharedMemorySize, GEMM_SMEM);

    enc_prep_kernel<<<TOTAL_BLOCKS, 256>>>(x, We, be, Wr);
    recur_feat<<<BN_, 128>>>(omega, ph_hist, wb_hist);
    gemm_hmma<<<dim3(4, 1024), 256, GEMM_SMEM>>>(br, logits);
}